// round 6
// baseline (speedup 1.0000x reference)
#include <cuda_runtime.h>
#include <math.h>

#define Bb 2
#define Ss 2048
#define Dd 1024
#define Hh 16
#define DHh 64

// Scratch (device globals: allowed; no runtime allocation)
__device__ float g_q[Bb*Hh*Ss*DHh];
__device__ float g_k[Bb*Hh*Ss*DHh];
__device__ float g_v[Bb*Hh*Ss*DHh];
__device__ float g_att[Bb*Ss*Dd];

// ---------------------------------------------------------------------------
// Fused QKV projection GEMM: [4096,1024] x [1024,1024]x3 -> head-major QKV
// 128x128 C-tile, BK=8, 8x8 per thread, 256 threads, gmem prefetch in regs.
// ---------------------------------------------------------------------------
__global__ __launch_bounds__(256) void qkv_gemm(
    const float* __restrict__ X,
    const float* __restrict__ Wq, const float* __restrict__ Wk, const float* __restrict__ Wv,
    const float* __restrict__ bq, const float* __restrict__ bk, const float* __restrict__ bv)
{
    __shared__ float As[8][128];
    __shared__ float Bs[8][128];

    const int nt    = blockIdx.x;          // 0..23  (3 weights x 8 n-tiles)
    const int which = nt >> 3;
    const float* W    = (which == 0) ? Wq : (which == 1) ? Wk : Wv;
    const float* bias = (which == 0) ? bq : (which == 1) ? bk : bv;
    float* OUT        = (which == 0) ? g_q : (which == 1) ? g_k : g_v;
    const int n0 = (nt & 7) * 128;
    const int m0 = blockIdx.y * 128;
    const int tid = threadIdx.x;

    const int a_row = tid >> 1;
    const int a_col = (tid & 1) * 4;
    const int b_row = tid >> 5;
    const int b_col = (tid & 31) * 4;
    const int rowBase = (tid >> 4) * 8;
    const int colBase = (tid & 15) * 8;

    float acc[8][8];
    #pragma unroll
    for (int i = 0; i < 8; i++)
        #pragma unroll
        for (int j = 0; j < 8; j++) acc[i][j] = 0.f;

    const float* Aptr = X + (size_t)(m0 + a_row) * Dd + a_col;
    const float* Bptr = W + (size_t)b_row * Dd + n0 + b_col;

    float4 a_nx = *(const float4*)Aptr;
    float4 b_nx = *(const float4*)Bptr;

    for (int k0 = 0; k0 < Dd; k0 += 8) {
        As[a_col+0][a_row] = a_nx.x;
        As[a_col+1][a_row] = a_nx.y;
        As[a_col+2][a_row] = a_nx.z;
        As[a_col+3][a_row] = a_nx.w;
        *(float4*)&Bs[b_row][b_col] = b_nx;
        __syncthreads();
        if (k0 + 8 < Dd) {
            a_nx = *(const float4*)(Aptr + k0 + 8);
            b_nx = *(const float4*)(Bptr + (size_t)(k0 + 8) * Dd);
        }
        #pragma unroll
        for (int kk = 0; kk < 8; kk++) {
            float ra[8], rb[8];
            *(float4*)&ra[0] = *(const float4*)&As[kk][rowBase];
            *(float4*)&ra[4] = *(const float4*)&As[kk][rowBase+4];
            *(float4*)&rb[0] = *(const float4*)&Bs[kk][colBase];
            *(float4*)&rb[4] = *(const float4*)&Bs[kk][colBase+4];
            #pragma unroll
            for (int i = 0; i < 8; i++)
                #pragma unroll
                for (int j = 0; j < 8; j++)
                    acc[i][j] = fmaf(ra[i], rb[j], acc[i][j]);
        }
        __syncthreads();
    }

    // Epilogue: bias add + scatter into [B,H,S,DH]. Thread's 8 cols lie in one head.
    float bvals[8];
    #pragma unroll
    for (int j = 0; j < 8; j++) bvals[j] = bias[n0 + colBase + j];
    const int d0  = n0 + colBase;
    const int hh  = d0 >> 6;
    const int dh0 = d0 & 63;
    #pragma unroll
    for (int i = 0; i < 8; i++) {
        const int m  = m0 + rowBase + i;
        const int bb = m >> 11;           // / S
        const int s  = m & (Ss - 1);
        float* dst = OUT + ((size_t)(bb * Hh + hh) * Ss + s) * DHh + dh0;
        float4 v0 = make_float4(acc[i][0]+bvals[0], acc[i][1]+bvals[1],
                                acc[i][2]+bvals[2], acc[i][3]+bvals[3]);
        float4 v1 = make_float4(acc[i][4]+bvals[4], acc[i][5]+bvals[5],
                                acc[i][6]+bvals[6], acc[i][7]+bvals[7]);
        *(float4*)dst       = v0;
        *(float4*)(dst + 4) = v1;
    }
}

// ---------------------------------------------------------------------------
// Flash attention (fp32, online softmax, ALiBi-softplus distance bias).
// Block: 64 queries of one (b,h). 256 threads as 16x16; 4x4 micro-tiles.
// Smem: Qs + Ks(XOR-swizzled, aliased as P) + Vs = exactly 48 KB.
// ---------------------------------------------------------------------------
__global__ __launch_bounds__(256) void attn_kernel(const float* __restrict__ slopes)
{
    __shared__ float Qs[64*64];
    __shared__ float Ks[64*64];   // swizzled K tile; reused as P tile
    __shared__ float Vs[64*64];

    const int bh = blockIdx.y;
    const int b  = bh >> 4;
    const int h  = bh & (Hh - 1);
    const int q0 = blockIdx.x * 64;
    const int tid = threadIdx.x;
    const int tx  = tid & 15;
    const int ty  = tid >> 4;

    const float sp = log1pf(expf(slopes[h]));   // softplus(slope)

    const size_t head_off = (size_t)(b * Hh + h) * Ss * DHh;
    const float* qptr = g_q + head_off;
    const float* kptr = g_k + head_off;
    const float* vptr = g_v + head_off;

    // Q tile, pre-scaled by 1/sqrt(DH) = 0.125 ; layout Qs[s*64+d]
    {
        const float4* src = (const float4*)(qptr + (size_t)q0 * DHh);
        float4* dst = (float4*)Qs;
        #pragma unroll
        for (int i = 0; i < 4; i++) {
            float4 v = src[tid + i*256];
            v.x *= 0.125f; v.y *= 0.125f; v.z *= 0.125f; v.w *= 0.125f;
            dst[tid + i*256] = v;
        }
    }

    float m_i[4], l_i[4], o[4][4];
    #pragma unroll
    for (int i = 0; i < 4; i++) {
        m_i[i] = -1e30f; l_i[i] = 0.f;
        #pragma unroll
        for (int j = 0; j < 4; j++) o[i][j] = 0.f;
    }

    const int x2 = tx * 2;   // read-side swizzle constant for rows 4tx..4tx+3

    for (int t = 0; t < Ss / 64; t++) {
        const int k0 = t * 64;
        __syncthreads();   // protect Ks/Vs from previous iteration readers
        {
            const float4* ksrc = (const float4*)(kptr + (size_t)k0 * DHh);
            const float4* vsrc = (const float4*)(vptr + (size_t)k0 * DHh);
            float4* vdst = (float4*)Vs;
            #pragma unroll
            for (int i = 0; i < 4; i++) {
                const int idx = tid + i*256;       // float4 index; 16 per row
                const int s   = idx >> 4;
                const int d0  = (idx & 15) << 2;
                const int xs  = (s >> 1) & 30;     // 2*((s>>2)&15)
                float4 kv = ksrc[idx];
                if (xs & 2) { float t0 = kv.x; kv.x = kv.z; kv.z = t0;
                              t0 = kv.y; kv.y = kv.w; kv.w = t0; }
                *(float4*)&Ks[s*64 + ((d0 ^ xs) & ~3)] = kv;
                vdst[idx] = vsrc[idx];
            }
        }
        __syncthreads();

        // S = (Q/8) K^T   (4x4 micro-tile, conflict-free swizzled K reads)
        float acc[4][4];
        #pragma unroll
        for (int i = 0; i < 4; i++)
            #pragma unroll
            for (int j = 0; j < 4; j++) acc[i][j] = 0.f;

        #pragma unroll 8
        for (int d = 0; d < 64; d++) {
            float rq[4], rk[4];
            #pragma unroll
            for (int i = 0; i < 4; i++) rq[i] = Qs[(ty*4+i)*64 + d];
            const int dx = d ^ x2;
            #pragma unroll
            for (int j = 0; j < 4; j++) rk[j] = Ks[(tx*4+j)*64 + dx];
            #pragma unroll
            for (int i = 0; i < 4; i++)
                #pragma unroll
                for (int j = 0; j < 4; j++)
                    acc[i][j] = fmaf(rq[i], rk[j], acc[i][j]);
        }

        // ALiBi bias + online softmax (row reductions over 16 contiguous lanes)
        #pragma unroll
        for (int i = 0; i < 4; i++) {
            const float rowp = (float)(q0 + ty*4 + i);
            float mt = -1e30f;
            #pragma unroll
            for (int j = 0; j < 4; j++) {
                const float dist = fabsf(rowp - (float)(k0 + tx*4 + j));
                acc[i][j] = fmaf(dist, -sp, acc[i][j]);
                mt = fmaxf(mt, acc[i][j]);
            }
            #pragma unroll
            for (int off = 1; off < 16; off <<= 1)
                mt = fmaxf(mt, __shfl_xor_sync(0xffffffffu, mt, off));
            const float mnew  = fmaxf(m_i[i], mt);
            const float scale = __expf(m_i[i] - mnew);
            m_i[i] = mnew;
            l_i[i] *= scale;
            #pragma unroll
            for (int j = 0; j < 4; j++) o[i][j] *= scale;
            float rs = 0.f;
            #pragma unroll
            for (int j = 0; j < 4; j++) {
                const float p = __expf(acc[i][j] - mnew);
                acc[i][j] = p;
                rs += p;
            }
            #pragma unroll
            for (int off = 1; off < 16; off <<= 1)
                rs += __shfl_xor_sync(0xffffffffu, rs, off);
            l_i[i] += rs;
        }

        __syncthreads();   // everyone done reading Ks as K
        #pragma unroll
        for (int i = 0; i < 4; i++)
            #pragma unroll
            for (int j = 0; j < 4; j++)
                Ks[(ty*4+i)*64 + tx*4 + j] = acc[i][j];   // P tile (plain layout)
        __syncthreads();

        // O += P @ V
        #pragma unroll 8
        for (int c = 0; c < 64; c++) {
            float rp[4];
            #pragma unroll
            for (int i = 0; i < 4; i++) rp[i] = Ks[(ty*4+i)*64 + c];
            const float4 v4 = *(const float4*)&Vs[c*64 + tx*4];
            #pragma unroll
            for (int i = 0; i < 4; i++) {
                o[i][0] = fmaf(rp[i], v4.x, o[i][0]);
                o[i][1] = fmaf(rp[i], v4.y, o[i][1]);
                o[i][2] = fmaf(rp[i], v4.z, o[i][2]);
                o[i][3] = fmaf(rp[i], v4.w, o[i][3]);
            }
        }
    }

    // Finalize: att[b][q0+r][h*64 + tx*4 + j]
    float* aptr = g_att + ((size_t)b * Ss + q0) * Dd + h * DHh + tx*4;
    #pragma unroll
    for (int i = 0; i < 4; i++) {
        const float inv = 1.f / l_i[i];
        float4 v = make_float4(o[i][0]*inv, o[i][1]*inv, o[i][2]*inv, o[i][3]*inv);
        *(float4*)(aptr + (size_t)(ty*4 + i) * Dd) = v;
    }
}

// ---------------------------------------------------------------------------
// Output projection GEMM: g_att [4096,1024] x Wo [1024,1024] + bo -> d_out
// ---------------------------------------------------------------------------
__global__ __launch_bounds__(256) void out_gemm(
    const float* __restrict__ Wo, const float* __restrict__ bo, float* __restrict__ out)
{
    __shared__ float As[8][128];
    __shared__ float Bs[8][128];

    const int n0 = blockIdx.x * 128;
    const int m0 = blockIdx.y * 128;
    const int tid = threadIdx.x;

    const int a_row = tid >> 1;
    const int a_col = (tid & 1) * 4;
    const int b_row = tid >> 5;
    const int b_col = (tid & 31) * 4;
    const int rowBase = (tid >> 4) * 8;
    const int colBase = (tid & 15) * 8;

    float acc[8][8];
    #pragma unroll
    for (int i = 0; i < 8; i++)
        #pragma unroll
        for (int j = 0; j < 8; j++) acc[i][j] = 0.f;

    const float* Aptr = g_att + (size_t)(m0 + a_row) * Dd + a_col;
    const float* Bptr = Wo + (size_t)b_row * Dd + n0 + b_col;

    float4 a_nx = *(const float4*)Aptr;
    float4 b_nx = *(const float4*)Bptr;

    for (int k0 = 0; k0 < Dd; k0 += 8) {
        As[a_col+0][a_row] = a_nx.x;
        As[a_col+1][a_row] = a_nx.y;
        As[a_col+2][a_row] = a_nx.z;
        As[a_col+3][a_row] = a_nx.w;
        *(float4*)&Bs[b_row][b_col] = b_nx;
        __syncthreads();
        if (k0 + 8 < Dd) {
            a_nx = *(const float4*)(Aptr + k0 + 8);
            b_nx = *(const float4*)(Bptr + (size_t)(k0 + 8) * Dd);
        }
        #pragma unroll
        for (int kk = 0; kk < 8; kk++) {
            float ra[8], rb[8];
            *(float4*)&ra[0] = *(const float4*)&As[kk][rowBase];
            *(float4*)&ra[4] = *(const float4*)&As[kk][rowBase+4];
            *(float4*)&rb[0] = *(const float4*)&Bs[kk][colBase];
            *(float4*)&rb[4] = *(const float4*)&Bs[kk][colBase+4];
            #pragma unroll
            for (int i = 0; i < 8; i++)
                #pragma unroll
                for (int j = 0; j < 8; j++)
                    acc[i][j] = fmaf(ra[i], rb[j], acc[i][j]);
        }
        __syncthreads();
    }

    float bvals[8];
    #pragma unroll
    for (int j = 0; j < 8; j++) bvals[j] = bo[n0 + colBase + j];
    #pragma unroll
    for (int i = 0; i < 8; i++) {
        float* dst = out + (size_t)(m0 + rowBase + i) * Dd + n0 + colBase;
        float4 v0 = make_float4(acc[i][0]+bvals[0], acc[i][1]+bvals[1],
                                acc[i][2]+bvals[2], acc[i][3]+bvals[3]);
        float4 v1 = make_float4(acc[i][4]+bvals[4], acc[i][5]+bvals[5],
                                acc[i][6]+bvals[6], acc[i][7]+bvals[7]);
        *(float4*)dst       = v0;
        *(float4*)(dst + 4) = v1;
    }
}

extern "C" void kernel_launch(void* const* d_in, const int* in_sizes, int n_in,
                              void* d_out, int out_size)
{
    const float* x      = (const float*)d_in[0];
    const float* Wq     = (const float*)d_in[1];
    const float* bq     = (const float*)d_in[2];
    const float* Wk     = (const float*)d_in[3];
    const float* bk     = (const float*)d_in[4];
    const float* Wv     = (const float*)d_in[5];
    const float* bv     = (const float*)d_in[6];
    const float* Wo     = (const float*)d_in[7];
    const float* bo     = (const float*)d_in[8];
    const float* slopes = (const float*)d_in[9];
    float* out = (float*)d_out;

    dim3 g1(24, 32);                 // 3 weights x 8 n-tiles, 32 m-tiles
    qkv_gemm<<<g1, 256>>>(x, Wq, Wk, Wv, bq, bk, bv);

    dim3 g2(Ss / 64, Bb * Hh);       // 32 q-tiles x 32 (b,h)
    attn_kernel<<<g2, 256>>>(slopes);

    dim3 g3(8, 32);                  // 8 n-tiles, 32 m-tiles
    out_gemm<<<g3, 256>>>(Wo, bo, out);
}

// round 8
// speedup vs baseline: 2.5763x; 2.5763x over previous
#include <cuda_runtime.h>
#include <math.h>
#include <stdint.h>

#define Bb 2
#define Ss 2048
#define Dd 1024
#define Hh 16
#define DHh 64
#define MM (Bb*Ss)

// Scratch (device globals: allowed; no runtime allocation). Plain [M][D] layout.
__device__ float g_q[MM*Dd];
__device__ float g_k[MM*Dd];
__device__ float g_v[MM*Dd];
__device__ float g_att[MM*Dd];

__device__ __forceinline__ uint32_t f2tf(float f) {
    uint32_t u;
    asm("cvt.rna.tf32.f32 %0, %1;" : "=r"(u) : "f"(f));
    return u;
}

__device__ __forceinline__ void mma_tf32(float* c,
                                         const uint32_t* a,
                                         uint32_t b0, uint32_t b1) {
    asm volatile("mma.sync.aligned.m16n8k8.row.col.f32.tf32.tf32.f32 "
        "{%0,%1,%2,%3}, {%4,%5,%6,%7}, {%8,%9}, {%0,%1,%2,%3};"
        : "+f"(c[0]), "+f"(c[1]), "+f"(c[2]), "+f"(c[3])
        : "r"(a[0]), "r"(a[1]), "r"(a[2]), "r"(a[3]), "r"(b0), "r"(b1));
}

// ---------------------------------------------------------------------------
// Tensor-core tf32 GEMM: C[M,128..] = A[M,1024] x W[1024,1024] + bias.
// mode 0: grid(24,32): fused QKV (weight picked by blockIdx.x>>3) -> g_q/g_k/g_v
// mode 1: grid(8,32):  A = g_att, W = Wo -> OUT param
// Block 128x128, BK=16, 8 warps (2m x 4n), warp tile 64x32, double-buffered.
// ---------------------------------------------------------------------------
__global__ __launch_bounds__(256, 2) void gemm_tc(
    const float* __restrict__ X,
    const float* __restrict__ W0, const float* __restrict__ W1, const float* __restrict__ W2,
    const float* __restrict__ b0p, const float* __restrict__ b1p, const float* __restrict__ b2p,
    float* __restrict__ OUTP, int mode)
{
    __shared__ uint32_t As[2][128][20];   // A row-major [m][k], pad->20
    __shared__ uint32_t Bs[2][16][136];   // W row-major [k][n], pad->136

    const float* A;
    const float* W;
    const float* bias;
    float* OUT;
    int n0;
    if (mode == 0) {
        const int sel = blockIdx.x >> 3;
        A = X;
        W    = (sel == 0) ? W0 : (sel == 1) ? W1 : W2;
        bias = (sel == 0) ? b0p : (sel == 1) ? b1p : b2p;
        OUT  = (sel == 0) ? g_q : (sel == 1) ? g_k : g_v;
        n0 = (blockIdx.x & 7) * 128;
    } else {
        A = g_att; W = W0; bias = b0p; OUT = OUTP;
        n0 = blockIdx.x * 128;
    }
    const int m0 = blockIdx.y * 128;
    const int tid  = threadIdx.x;
    const int lane = tid & 31;
    const int warp = tid >> 5;
    const int wm = warp & 1;
    const int wn = warp >> 1;
    const int lr = lane >> 2;
    const int lc = lane & 3;

    float c[4][4][4];
    #pragma unroll
    for (int mi = 0; mi < 4; mi++)
        #pragma unroll
        for (int ni = 0; ni < 4; ni++)
            #pragma unroll
            for (int q = 0; q < 4; q++) c[mi][ni][q] = 0.f;

    // loader indices
    const int ar  = tid >> 2;     // A rows: ar, ar+64
    const int ac4 = tid & 3;      // A float4 col within 16-k tile
    const int bkr = tid >> 5;     // B k-rows: bkr, bkr+8
    const int bn4 = tid & 31;     // B float4 col within 128-n tile

    // preload tile 0
    {
        float4 av0 = *(const float4*)&A[(size_t)(m0 + ar) * Dd + 4*ac4];
        float4 av1 = *(const float4*)&A[(size_t)(m0 + ar + 64) * Dd + 4*ac4];
        float4 bv0 = *(const float4*)&W[(size_t)(bkr) * Dd + n0 + 4*bn4];
        float4 bv1 = *(const float4*)&W[(size_t)(bkr + 8) * Dd + n0 + 4*bn4];
        *(uint4*)&As[0][ar][4*ac4]    = make_uint4(f2tf(av0.x), f2tf(av0.y), f2tf(av0.z), f2tf(av0.w));
        *(uint4*)&As[0][ar+64][4*ac4] = make_uint4(f2tf(av1.x), f2tf(av1.y), f2tf(av1.z), f2tf(av1.w));
        *(uint4*)&Bs[0][bkr][4*bn4]   = make_uint4(f2tf(bv0.x), f2tf(bv0.y), f2tf(bv0.z), f2tf(bv0.w));
        *(uint4*)&Bs[0][bkr+8][4*bn4] = make_uint4(f2tf(bv1.x), f2tf(bv1.y), f2tf(bv1.z), f2tf(bv1.w));
    }
    __syncthreads();

    int buf = 0;
    for (int kt = 0; kt < 64; kt++) {
        float4 av0, av1, bv0, bv1;
        const int kn = (kt + 1) * 16;
        if (kt < 63) {
            av0 = *(const float4*)&A[(size_t)(m0 + ar) * Dd + kn + 4*ac4];
            av1 = *(const float4*)&A[(size_t)(m0 + ar + 64) * Dd + kn + 4*ac4];
            bv0 = *(const float4*)&W[(size_t)(kn + bkr) * Dd + n0 + 4*bn4];
            bv1 = *(const float4*)&W[(size_t)(kn + bkr + 8) * Dd + n0 + 4*bn4];
        }
        #pragma unroll
        for (int kc = 0; kc < 2; kc++) {
            uint32_t af[4][4], bf[4][2];
            #pragma unroll
            for (int mi = 0; mi < 4; mi++) {
                const int m = wm*64 + mi*16 + lr;
                af[mi][0] = As[buf][m][kc*8 + lc];
                af[mi][1] = As[buf][m + 8][kc*8 + lc];
                af[mi][2] = As[buf][m][kc*8 + lc + 4];
                af[mi][3] = As[buf][m + 8][kc*8 + lc + 4];
            }
            #pragma unroll
            for (int ni = 0; ni < 4; ni++) {
                const int n = wn*32 + ni*8 + lr;
                bf[ni][0] = Bs[buf][kc*8 + lc][n];
                bf[ni][1] = Bs[buf][kc*8 + lc + 4][n];
            }
            #pragma unroll
            for (int mi = 0; mi < 4; mi++)
                #pragma unroll
                for (int ni = 0; ni < 4; ni++)
                    mma_tf32(c[mi][ni], af[mi], bf[ni][0], bf[ni][1]);
        }
        if (kt < 63) {
            const int nb = buf ^ 1;
            *(uint4*)&As[nb][ar][4*ac4]    = make_uint4(f2tf(av0.x), f2tf(av0.y), f2tf(av0.z), f2tf(av0.w));
            *(uint4*)&As[nb][ar+64][4*ac4] = make_uint4(f2tf(av1.x), f2tf(av1.y), f2tf(av1.z), f2tf(av1.w));
            *(uint4*)&Bs[nb][bkr][4*bn4]   = make_uint4(f2tf(bv0.x), f2tf(bv0.y), f2tf(bv0.z), f2tf(bv0.w));
            *(uint4*)&Bs[nb][bkr+8][4*bn4] = make_uint4(f2tf(bv1.x), f2tf(bv1.y), f2tf(bv1.z), f2tf(bv1.w));
        }
        __syncthreads();
        buf ^= 1;
    }

    // Epilogue
    #pragma unroll
    for (int mi = 0; mi < 4; mi++) {
        const int row = m0 + wm*64 + mi*16 + lr;
        #pragma unroll
        for (int ni = 0; ni < 4; ni++) {
            const int col = n0 + wn*32 + ni*8 + 2*lc;
            const float bx = bias[col], by = bias[col + 1];
            float2 v0 = make_float2(c[mi][ni][0] + bx, c[mi][ni][1] + by);
            float2 v1 = make_float2(c[mi][ni][2] + bx, c[mi][ni][3] + by);
            *(float2*)&OUT[(size_t)row * Dd + col]       = v0;
            *(float2*)&OUT[(size_t)(row + 8) * Dd + col] = v1;
        }
    }
}

// ---------------------------------------------------------------------------
// Flash attention, tf32 tensor cores.
// Block: 64 queries of one (b,h); 8 warps (4 q-quarters x 2 halves).
// Q frags persist in regs; K/P share a buffer; SIMT online softmax.
// ---------------------------------------------------------------------------
__global__ __launch_bounds__(256, 2) void attn_tc(const float* __restrict__ slopes)
{
    __shared__ uint32_t KP[64][68];  // K tile [key][d] (tf32); then raw S; then P (tf32)
    __shared__ uint32_t Vs[64][72];  // V tile [t][d] (tf32)
    __shared__ float s_scale[64];
    __shared__ float s_l[64];

    const int tid  = threadIdx.x;
    const int lane = tid & 31;
    const int warp = tid >> 5;
    const int wq = warp >> 1;    // 0..3 : q quarter (16 rows)
    const int wh = warp & 1;     // 0..1 : key half (S) / d half (PV)
    const int lr = lane >> 2;
    const int lc = lane & 3;
    const int b  = blockIdx.y >> 4;
    const int h  = blockIdx.y & (Hh - 1);
    const int q0 = blockIdx.x * 64;

    const float sp = log1pf(expf(slopes[h]));

    // Persistent Q fragments (scale 1/8 folded)
    uint32_t qf[8][4];
    {
        const size_t r0 = (size_t)(b*Ss + q0 + wq*16 + lr) * Dd + h*DHh;
        const size_t r1 = r0 + (size_t)8 * Dd;
        #pragma unroll
        for (int kc = 0; kc < 8; kc++) {
            const int cc = kc*8 + lc;
            qf[kc][0] = f2tf(0.125f * g_q[r0 + cc]);
            qf[kc][1] = f2tf(0.125f * g_q[r1 + cc]);
            qf[kc][2] = f2tf(0.125f * g_q[r0 + cc + 4]);
            qf[kc][3] = f2tf(0.125f * g_q[r1 + cc + 4]);
        }
    }

    float o[4][4];
    #pragma unroll
    for (int ni = 0; ni < 4; ni++)
        #pragma unroll
        for (int q = 0; q < 4; q++) o[ni][q] = 0.f;

    const int srow = tid >> 2;    // softmax: 4 threads per row
    const int schk = tid & 3;
    const float qpos = (float)(q0 + srow);
    float m_own = -1e30f, l_own = 0.f;

    for (int t = 0; t < Ss/64; t++) {
        const int k0 = t * 64;
        __syncthreads();   // prev iter PV reads of KP/Vs + s_scale done
        // Load K, V tiles (cvt tf32)
        #pragma unroll
        for (int i = 0; i < 4; i++) {
            const int idx = tid + i*256;
            const int key = idx >> 4;
            const int c4  = (idx & 15) * 4;
            const size_t g = (size_t)(b*Ss + k0 + key) * Dd + h*DHh + c4;
            float4 kv = *(const float4*)&g_k[g];
            float4 vv = *(const float4*)&g_v[g];
            *(uint4*)&KP[key][c4] = make_uint4(f2tf(kv.x), f2tf(kv.y), f2tf(kv.z), f2tf(kv.w));
            *(uint4*)&Vs[key][c4] = make_uint4(f2tf(vv.x), f2tf(vv.y), f2tf(vv.z), f2tf(vv.w));
        }
        __syncthreads();

        // S = Q K^T (warp: 16q x 32key)
        float sc[4][4];
        #pragma unroll
        for (int ni = 0; ni < 4; ni++)
            #pragma unroll
            for (int q = 0; q < 4; q++) sc[ni][q] = 0.f;
        #pragma unroll
        for (int kc = 0; kc < 8; kc++) {
            uint32_t kb0[4], kb1[4];
            #pragma unroll
            for (int ni = 0; ni < 4; ni++) {
                const int key = wh*32 + ni*8 + lr;
                kb0[ni] = KP[key][kc*8 + lc];
                kb1[ni] = KP[key][kc*8 + lc + 4];
            }
            #pragma unroll
            for (int ni = 0; ni < 4; ni++)
                mma_tf32(sc[ni], qf[kc], kb0[ni], kb1[ni]);
        }
        __syncthreads();   // all K reads done before overwrite

        // Scatter raw logits into KP
        {
            const int r = wq*16 + lr;
            #pragma unroll
            for (int ni = 0; ni < 4; ni++) {
                const int cc = wh*32 + ni*8 + 2*lc;
                KP[r][cc]       = __float_as_uint(sc[ni][0]);
                KP[r][cc + 1]   = __float_as_uint(sc[ni][1]);
                KP[r + 8][cc]   = __float_as_uint(sc[ni][2]);
                KP[r + 8][cc+1] = __float_as_uint(sc[ni][3]);
            }
        }
        __syncthreads();

        // Online softmax with ALiBi bias (4 threads per row, 16 cols each)
        float mt = -1e30f;
        #pragma unroll
        for (int j = 0; j < 16; j++) {
            const int col = schk*16 + j;
            float x = __uint_as_float(KP[srow][col]);
            x -= sp * fabsf(qpos - (float)(k0 + col));
            KP[srow][col] = __float_as_uint(x);
            mt = fmaxf(mt, x);
        }
        mt = fmaxf(mt, __shfl_xor_sync(0xffffffffu, mt, 1));
        mt = fmaxf(mt, __shfl_xor_sync(0xffffffffu, mt, 2));
        const float mnew = fmaxf(m_own, mt);
        const float scl  = __expf(m_own - mnew);
        m_own = mnew;
        float rs = 0.f;
        #pragma unroll
        for (int j = 0; j < 16; j++) {
            const int col = schk*16 + j;
            const float p = __expf(__uint_as_float(KP[srow][col]) - mnew);
            KP[srow][col] = f2tf(p);
            rs += p;
        }
        rs += __shfl_xor_sync(0xffffffffu, rs, 1);
        rs += __shfl_xor_sync(0xffffffffu, rs, 2);
        l_own = l_own * scl + rs;
        if (schk == 0) s_scale[srow] = scl;
        __syncthreads();

        // O = O*scale + P V  (warp: 16q x 32d)
        {
            const float s0 = s_scale[wq*16 + lr];
            const float s1 = s_scale[wq*16 + lr + 8];
            #pragma unroll
            for (int ni = 0; ni < 4; ni++) {
                o[ni][0] *= s0; o[ni][1] *= s0;
                o[ni][2] *= s1; o[ni][3] *= s1;
            }
            const int r = wq*16 + lr;
            #pragma unroll
            for (int kc = 0; kc < 8; kc++) {
                uint32_t pa[4];
                pa[0] = KP[r][kc*8 + lc];
                pa[1] = KP[r + 8][kc*8 + lc];
                pa[2] = KP[r][kc*8 + lc + 4];
                pa[3] = KP[r + 8][kc*8 + lc + 4];
                #pragma unroll
                for (int ni = 0; ni < 4; ni++) {
                    const int d = wh*32 + ni*8 + lr;
                    mma_tf32(o[ni], pa, Vs[kc*8 + lc][d], Vs[kc*8 + lc + 4][d]);
                }
            }
        }
    }

    __syncthreads();
    if (schk == 0) s_l[srow] = l_own;
    __syncthreads();
    {
        const float inv0 = 1.f / s_l[wq*16 + lr];
        const float inv1 = 1.f / s_l[wq*16 + lr + 8];
        const size_t r0 = (size_t)(b*Ss + q0 + wq*16 + lr) * Dd + h*DHh;
        #pragma unroll
        for (int ni = 0; ni < 4; ni++) {
            const int cc = wh*32 + ni*8 + 2*lc;
            *(float2*)&g_att[r0 + cc] = make_float2(o[ni][0]*inv0, o[ni][1]*inv0);
            *(float2*)&g_att[r0 + (size_t)8*Dd + cc] = make_float2(o[ni][2]*inv1, o[ni][3]*inv1);
        }
    }
}

extern "C" void kernel_launch(void* const* d_in, const int* in_sizes, int n_in,
                              void* d_out, int out_size)
{
    const float* x      = (const float*)d_in[0];
    const float* Wq     = (const float*)d_in[1];
    const float* bq     = (const float*)d_in[2];
    const float* Wk     = (const float*)d_in[3];
    const float* bk     = (const float*)d_in[4];
    const float* Wv     = (const float*)d_in[5];
    const float* bv     = (const float*)d_in[6];
    const float* Wo     = (const float*)d_in[7];
    const float* bo     = (const float*)d_in[8];
    const float* slopes = (const float*)d_in[9];
    float* out = (float*)d_out;

    dim3 g1(24, 32);                 // fused QKV
    gemm_tc<<<g1, 256>>>(x, Wq, Wk, Wv, bq, bk, bv, nullptr, 0);

    dim3 g2(Ss / 64, Bb * Hh);       // 32 q-tiles x 32 (b,h)
    attn_tc<<<g2, 256>>>(slopes);

    dim3 g3(8, 32);                  // O projection
    gemm_tc<<<g3, 256>>>(nullptr, Wo, nullptr, nullptr, bo, nullptr, nullptr, out, 1);
}

// round 10
// speedup vs baseline: 2.9816x; 1.1573x over previous
#include <cuda_runtime.h>
#include <math.h>
#include <stdint.h>

#define Bb 2
#define Ss 2048
#define Dd 1024
#define Hh 16
#define DHh 64
#define MM (Bb*Ss)

// Scratch (device globals). Plain [M][D] layout.
__device__ float g_q[MM*Dd];
__device__ float g_k[MM*Dd];
__device__ float g_v[MM*Dd];
__device__ float g_att[MM*Dd];

__device__ __forceinline__ uint32_t f2tf(float f) {
    uint32_t u;
    asm("cvt.rna.tf32.f32 %0, %1;" : "=r"(u) : "f"(f));
    return u;
}

__device__ __forceinline__ void mma_tf32(float* c,
                                         const uint32_t* a,
                                         uint32_t b0, uint32_t b1) {
    asm volatile("mma.sync.aligned.m16n8k8.row.col.f32.tf32.tf32.f32 "
        "{%0,%1,%2,%3}, {%4,%5,%6,%7}, {%8,%9}, {%0,%1,%2,%3};"
        : "+f"(c[0]), "+f"(c[1]), "+f"(c[2]), "+f"(c[3])
        : "r"(a[0]), "r"(a[1]), "r"(a[2]), "r"(a[3]), "r"(b0), "r"(b1));
}

// ---------------------------------------------------------------------------
// tf32 GEMM: block 128x128, BK=16, 4 warps, warp tile 64x64 (high reuse).
// mode 0: grid(24,32): fused QKV -> g_q/g_k/g_v.  mode 1: grid(8,32): O-proj.
// ---------------------------------------------------------------------------
__global__ __launch_bounds__(128, 2) void gemm_tc(
    const float* __restrict__ X,
    const float* __restrict__ W0, const float* __restrict__ W1, const float* __restrict__ W2,
    const float* __restrict__ b0p, const float* __restrict__ b1p, const float* __restrict__ b2p,
    float* __restrict__ OUTP, int mode)
{
    __shared__ uint32_t As[2][128][20];   // A [m][k], pad 20
    __shared__ uint32_t Bs[2][16][136];   // W [k][n], pad 136

    const float* A;
    const float* W;
    const float* bias;
    float* OUT;
    int n0;
    if (mode == 0) {
        const int sel = blockIdx.x >> 3;
        A = X;
        W    = (sel == 0) ? W0 : (sel == 1) ? W1 : W2;
        bias = (sel == 0) ? b0p : (sel == 1) ? b1p : b2p;
        OUT  = (sel == 0) ? g_q : (sel == 1) ? g_k : g_v;
        n0 = (blockIdx.x & 7) * 128;
    } else {
        A = g_att; W = W0; bias = b0p; OUT = OUTP;
        n0 = blockIdx.x * 128;
    }
    const int m0 = blockIdx.y * 128;
    const int tid  = threadIdx.x;
    const int lane = tid & 31;
    const int warp = tid >> 5;           // 0..3
    const int wm = warp & 1;
    const int wn = warp >> 1;
    const int lr = lane >> 2;
    const int lc = lane & 3;

    float c[4][8][4];
    #pragma unroll
    for (int mi = 0; mi < 4; mi++)
        #pragma unroll
        for (int ni = 0; ni < 8; ni++)
            #pragma unroll
            for (int q = 0; q < 4; q++) c[mi][ni][q] = 0.f;

    const int ar  = tid >> 2;   // 0..31 : A rows ar + 32u
    const int ac4 = tid & 3;    // float4 col in 16-k tile
    const int bkr = tid >> 5;   // 0..3  : B k-rows bkr + 4u
    const int bn4 = tid & 31;   // float4 col in 128-n tile

    float4 av[4], bv[4];
    #pragma unroll
    for (int u = 0; u < 4; u++) {
        av[u] = *(const float4*)&A[(size_t)(m0 + ar + 32*u) * Dd + 4*ac4];
        bv[u] = *(const float4*)&W[(size_t)(bkr + 4*u) * Dd + n0 + 4*bn4];
    }
    #pragma unroll
    for (int u = 0; u < 4; u++) {
        *(uint4*)&As[0][ar + 32*u][4*ac4] =
            make_uint4(f2tf(av[u].x), f2tf(av[u].y), f2tf(av[u].z), f2tf(av[u].w));
        *(uint4*)&Bs[0][bkr + 4*u][4*bn4] =
            make_uint4(f2tf(bv[u].x), f2tf(bv[u].y), f2tf(bv[u].z), f2tf(bv[u].w));
    }
    __syncthreads();

    int buf = 0;
    for (int kt = 0; kt < 64; kt++) {
        const int kn = (kt + 1) * 16;
        if (kt < 63) {
            #pragma unroll
            for (int u = 0; u < 4; u++) {
                av[u] = *(const float4*)&A[(size_t)(m0 + ar + 32*u) * Dd + kn + 4*ac4];
                bv[u] = *(const float4*)&W[(size_t)(kn + bkr + 4*u) * Dd + n0 + 4*bn4];
            }
        }
        #pragma unroll
        for (int kc = 0; kc < 2; kc++) {
            uint32_t af[4][4], bf[8][2];
            #pragma unroll
            for (int mi = 0; mi < 4; mi++) {
                const int m = wm*64 + mi*16 + lr;
                af[mi][0] = As[buf][m][kc*8 + lc];
                af[mi][1] = As[buf][m + 8][kc*8 + lc];
                af[mi][2] = As[buf][m][kc*8 + lc + 4];
                af[mi][3] = As[buf][m + 8][kc*8 + lc + 4];
            }
            #pragma unroll
            for (int ni = 0; ni < 8; ni++) {
                const int n = wn*64 + ni*8 + lr;
                bf[ni][0] = Bs[buf][kc*8 + lc][n];
                bf[ni][1] = Bs[buf][kc*8 + lc + 4][n];
            }
            #pragma unroll
            for (int mi = 0; mi < 4; mi++)
                #pragma unroll
                for (int ni = 0; ni < 8; ni++)
                    mma_tf32(c[mi][ni], af[mi], bf[ni][0], bf[ni][1]);
        }
        if (kt < 63) {
            const int nb = buf ^ 1;
            #pragma unroll
            for (int u = 0; u < 4; u++) {
                *(uint4*)&As[nb][ar + 32*u][4*ac4] =
                    make_uint4(f2tf(av[u].x), f2tf(av[u].y), f2tf(av[u].z), f2tf(av[u].w));
                *(uint4*)&Bs[nb][bkr + 4*u][4*bn4] =
                    make_uint4(f2tf(bv[u].x), f2tf(bv[u].y), f2tf(bv[u].z), f2tf(bv[u].w));
            }
        }
        __syncthreads();
        buf ^= 1;
    }

    #pragma unroll
    for (int mi = 0; mi < 4; mi++) {
        const int row = m0 + wm*64 + mi*16 + lr;
        #pragma unroll
        for (int ni = 0; ni < 8; ni++) {
            const int col = n0 + wn*64 + ni*8 + 2*lc;
            const float bx = bias[col], by = bias[col + 1];
            *(float2*)&OUT[(size_t)row * Dd + col] =
                make_float2(c[mi][ni][0] + bx, c[mi][ni][1] + by);
            *(float2*)&OUT[(size_t)(row + 8) * Dd + col] =
                make_float2(c[mi][ni][2] + bx, c[mi][ni][3] + by);
        }
    }
}

// ---------------------------------------------------------------------------
// Flash attention, tf32 MMA, 128 queries/block, in-register softmax.
// 8 warps = 4 q-groups (32q) x 2 key-halves (32k). P stays in registers
// (C-frag -> A-frag via quad shuffles). Partial O combined across key halves
// at the end through reused K/V smem.
// ---------------------------------------------------------------------------
__global__ __launch_bounds__(256, 1) void attn_tc(const float* __restrict__ slopes)
{
    __shared__ __align__(16) uint32_t SP[64*68 + 64*72];  // Ks[64][68] | Vs[64][72]
    __shared__ float s_red[2][2][128];                    // [phase][kh][row]

    uint32_t* Ks = SP;
    uint32_t* Vs = SP + 64*68;

    const int tid  = threadIdx.x;
    const int lane = tid & 31;
    const int warp = tid >> 5;
    const int qw = warp >> 1;      // 0..3 : q group (32 rows)
    const int kh = warp & 1;       // 0..1 : key half
    const int lr = lane >> 2;
    const int lc = lane & 3;
    const int b  = blockIdx.y >> 4;
    const int h  = blockIdx.y & (Hh - 1);
    const int q0 = blockIdx.x * 128;

    const float sp = log1pf(expf(slopes[h]));
    const unsigned FULL = 0xffffffffu;

    // Persistent Q fragments (rows qw*32 + mi*16 + lr(+8)), scale 1/8 folded.
    uint32_t qf[2][8][4];
    {
        const size_t rq = (size_t)(b*Ss + q0 + qw*32 + lr) * Dd + h*DHh;
        #pragma unroll
        for (int mi = 0; mi < 2; mi++) {
            const size_t r0 = rq + (size_t)(mi*16) * Dd;
            const size_t r1 = r0 + (size_t)8 * Dd;
            #pragma unroll
            for (int kc = 0; kc < 8; kc++) {
                const int cc = kc*8 + lc;
                qf[mi][kc][0] = f2tf(0.125f * g_q[r0 + cc]);
                qf[mi][kc][1] = f2tf(0.125f * g_q[r1 + cc]);
                qf[mi][kc][2] = f2tf(0.125f * g_q[r0 + cc + 4]);
                qf[mi][kc][3] = f2tf(0.125f * g_q[r1 + cc + 4]);
            }
        }
    }

    float o[2][8][4];
    #pragma unroll
    for (int mi = 0; mi < 2; mi++)
        #pragma unroll
        for (int nd = 0; nd < 8; nd++)
            #pragma unroll
            for (int q = 0; q < 4; q++) o[mi][nd][q] = 0.f;

    float m_r[2][2], l_r[2][2];
    #pragma unroll
    for (int mi = 0; mi < 2; mi++)
        #pragma unroll
        for (int rh = 0; rh < 2; rh++) { m_r[mi][rh] = -1e30f; l_r[mi][rh] = 0.f; }

    const int rl0 = qw*32 + lr;             // local row base (mi*16 added later)
    const float qr_base = (float)(q0 + qw*32 + lr);

    for (int t = 0; t < Ss/64; t++) {
        const int k0 = t * 64;
        __syncthreads();   // previous iter's smem readers done
        // Load K/V tiles (tf32)
        #pragma unroll
        for (int i = 0; i < 4; i++) {
            const int idx = tid + i*256;
            const int key = idx >> 4;
            const int c4  = (idx & 15) * 4;
            const size_t g = (size_t)(b*Ss + k0 + key) * Dd + h*DHh + c4;
            float4 kv = *(const float4*)&g_k[g];
            float4 vv = *(const float4*)&g_v[g];
            *(uint4*)&Ks[key*68 + c4] = make_uint4(f2tf(kv.x), f2tf(kv.y), f2tf(kv.z), f2tf(kv.w));
            *(uint4*)&Vs[key*72 + c4] = make_uint4(f2tf(vv.x), f2tf(vv.y), f2tf(vv.z), f2tf(vv.w));
        }
        __syncthreads();

        // S = Q K^T  (warp: 32q x 32key)
        float sc[2][4][4];
        #pragma unroll
        for (int mi = 0; mi < 2; mi++)
            #pragma unroll
            for (int ni = 0; ni < 4; ni++)
                #pragma unroll
                for (int q = 0; q < 4; q++) sc[mi][ni][q] = 0.f;
        #pragma unroll
        for (int kc = 0; kc < 8; kc++) {
            uint32_t kb0[4], kb1[4];
            #pragma unroll
            for (int ni = 0; ni < 4; ni++) {
                const int key = kh*32 + ni*8 + lr;
                kb0[ni] = Ks[key*68 + kc*8 + lc];
                kb1[ni] = Ks[key*68 + kc*8 + lc + 4];
            }
            #pragma unroll
            for (int mi = 0; mi < 2; mi++)
                #pragma unroll
                for (int ni = 0; ni < 4; ni++)
                    mma_tf32(sc[mi][ni], qf[mi][kc], kb0[ni], kb1[ni]);
        }

        // ALiBi bias + per-warp tile row max (quad reduce)
        float pm[2][2];
        #pragma unroll
        for (int mi = 0; mi < 2; mi++) {
            const float qr0 = qr_base + (float)(mi*16);
            const float qr1 = qr0 + 8.f;
            float p0 = -1e30f, p1 = -1e30f;
            #pragma unroll
            for (int ni = 0; ni < 4; ni++) {
                const float kp = (float)(k0 + kh*32 + ni*8 + 2*lc);
                sc[mi][ni][0] = fmaf(-sp, fabsf(qr0 - kp),       sc[mi][ni][0]);
                sc[mi][ni][1] = fmaf(-sp, fabsf(qr0 - (kp+1.f)), sc[mi][ni][1]);
                sc[mi][ni][2] = fmaf(-sp, fabsf(qr1 - kp),       sc[mi][ni][2]);
                sc[mi][ni][3] = fmaf(-sp, fabsf(qr1 - (kp+1.f)), sc[mi][ni][3]);
                p0 = fmaxf(p0, fmaxf(sc[mi][ni][0], sc[mi][ni][1]));
                p1 = fmaxf(p1, fmaxf(sc[mi][ni][2], sc[mi][ni][3]));
            }
            p0 = fmaxf(p0, __shfl_xor_sync(FULL, p0, 1));
            p0 = fmaxf(p0, __shfl_xor_sync(FULL, p0, 2));
            p1 = fmaxf(p1, __shfl_xor_sync(FULL, p1, 1));
            p1 = fmaxf(p1, __shfl_xor_sync(FULL, p1, 2));
            pm[mi][0] = p0; pm[mi][1] = p1;
            if (lc == 0) {
                s_red[0][kh][rl0 + mi*16]     = p0;
                s_red[0][kh][rl0 + mi*16 + 8] = p1;
            }
        }
        __syncthreads();

        // Global row max, exp, partial sums
        float scl[2][2], mn[2][2];
        #pragma unroll
        for (int mi = 0; mi < 2; mi++)
            #pragma unroll
            for (int rh = 0; rh < 2; rh++) {
                const float mo = s_red[0][kh ^ 1][rl0 + mi*16 + rh*8];
                const float mnew = fmaxf(m_r[mi][rh], fmaxf(pm[mi][rh], mo));
                scl[mi][rh] = __expf(m_r[mi][rh] - mnew);
                m_r[mi][rh] = mnew;
                mn[mi][rh] = mnew;
            }
        #pragma unroll
        for (int mi = 0; mi < 2; mi++) {
            float s0 = 0.f, s1 = 0.f;
            #pragma unroll
            for (int ni = 0; ni < 4; ni++) {
                sc[mi][ni][0] = __expf(sc[mi][ni][0] - mn[mi][0]);
                sc[mi][ni][1] = __expf(sc[mi][ni][1] - mn[mi][0]);
                sc[mi][ni][2] = __expf(sc[mi][ni][2] - mn[mi][1]);
                sc[mi][ni][3] = __expf(sc[mi][ni][3] - mn[mi][1]);
                s0 += sc[mi][ni][0] + sc[mi][ni][1];
                s1 += sc[mi][ni][2] + sc[mi][ni][3];
            }
            s0 += __shfl_xor_sync(FULL, s0, 1);
            s0 += __shfl_xor_sync(FULL, s0, 2);
            s1 += __shfl_xor_sync(FULL, s1, 1);
            s1 += __shfl_xor_sync(FULL, s1, 2);
            if (lc == 0) {
                s_red[1][kh][rl0 + mi*16]     = s0;
                s_red[1][kh][rl0 + mi*16 + 8] = s1;
            }
            pm[mi][0] = s0; pm[mi][1] = s1;   // reuse pm as own-sum
        }
        __syncthreads();
        #pragma unroll
        for (int mi = 0; mi < 2; mi++)
            #pragma unroll
            for (int rh = 0; rh < 2; rh++) {
                const float so = s_red[1][kh ^ 1][rl0 + mi*16 + rh*8];
                l_r[mi][rh] = l_r[mi][rh] * scl[mi][rh] + pm[mi][rh] + so;
            }

        // Rescale O, transform P (C-frag -> A-frag), accumulate PV
        #pragma unroll
        for (int mi = 0; mi < 2; mi++)
            #pragma unroll
            for (int nd = 0; nd < 8; nd++) {
                o[mi][nd][0] *= scl[mi][0]; o[mi][nd][1] *= scl[mi][0];
                o[mi][nd][2] *= scl[mi][1]; o[mi][nd][3] *= scl[mi][1];
            }
        const int qb2 = lane & 28;
        const int s0l = qb2 + (lc >> 1);
        const int s1l = s0l + 2;
        const bool odd = (lc & 1);
        #pragma unroll
        for (int ni = 0; ni < 4; ni++) {          // ni = key-chunk of PV
            uint32_t pa[2][4];
            #pragma unroll
            for (int mi = 0; mi < 2; mi++) {
                float x0 = __shfl_sync(FULL, sc[mi][ni][0], s0l);
                float x1 = __shfl_sync(FULL, sc[mi][ni][1], s0l);
                float y0 = __shfl_sync(FULL, sc[mi][ni][2], s0l);
                float y1 = __shfl_sync(FULL, sc[mi][ni][3], s0l);
                float z0 = __shfl_sync(FULL, sc[mi][ni][0], s1l);
                float z1 = __shfl_sync(FULL, sc[mi][ni][1], s1l);
                float w0 = __shfl_sync(FULL, sc[mi][ni][2], s1l);
                float w1 = __shfl_sync(FULL, sc[mi][ni][3], s1l);
                pa[mi][0] = f2tf(odd ? x1 : x0);
                pa[mi][1] = f2tf(odd ? y1 : y0);
                pa[mi][2] = f2tf(odd ? z1 : z0);
                pa[mi][3] = f2tf(odd ? w1 : w0);
            }
            const int krow0 = (kh*32 + ni*8 + lc) * 72;
            const int krow1 = (kh*32 + ni*8 + lc + 4) * 72;
            #pragma unroll
            for (int nd = 0; nd < 8; nd++) {
                const uint32_t b0 = Vs[krow0 + nd*8 + lr];
                const uint32_t b1 = Vs[krow1 + nd*8 + lr];
                mma_tf32(o[0][nd], pa[0], b0, b1);
                mma_tf32(o[1][nd], pa[1], b0, b1);
            }
        }
    }

    // Combine the two key-half partials through reused K/V smem.
    __syncthreads();
    float* Ob = (float*)SP;   // [128][68]
    if (kh == 0) {
        #pragma unroll
        for (int mi = 0; mi < 2; mi++) {
            const int r0 = (rl0 + mi*16) * 68;
            const int r1 = r0 + 8*68;
            #pragma unroll
            for (int nd = 0; nd < 8; nd++) {
                const int cc = nd*8 + 2*lc;
                *(float2*)&Ob[r0 + cc] = make_float2(o[mi][nd][0], o[mi][nd][1]);
                *(float2*)&Ob[r1 + cc] = make_float2(o[mi][nd][2], o[mi][nd][3]);
            }
        }
    }
    __syncthreads();
    if (kh == 1) {
        #pragma unroll
        for (int mi = 0; mi < 2; mi++) {
            const float i0 = 1.f / l_r[mi][0];
            const float i1 = 1.f / l_r[mi][1];
            const int r0 = (rl0 + mi*16) * 68;
            const int r1 = r0 + 8*68;
            const size_t g0 = (size_t)(b*Ss + q0 + rl0 + mi*16) * Dd + h*DHh;
            const size_t g1 = g0 + (size_t)8 * Dd;
            #pragma unroll
            for (int nd = 0; nd < 8; nd++) {
                const int cc = nd*8 + 2*lc;
                float2 p0 = *(float2*)&Ob[r0 + cc];
                float2 p1 = *(float2*)&Ob[r1 + cc];
                *(float2*)&g_att[g0 + cc] =
                    make_float2((o[mi][nd][0] + p0.x) * i0, (o[mi][nd][1] + p0.y) * i0);
                *(float2*)&g_att[g1 + cc] =
                    make_float2((o[mi][nd][2] + p1.x) * i1, (o[mi][nd][3] + p1.y) * i1);
            }
        }
    }
}

extern "C" void kernel_launch(void* const* d_in, const int* in_sizes, int n_in,
                              void* d_out, int out_size)
{
    const float* x      = (const float*)d_in[0];
    const float* Wq     = (const float*)d_in[1];
    const float* bq     = (const float*)d_in[2];
    const float* Wk     = (const float*)d_in[3];
    const float* bk     = (const float*)d_in[4];
    const float* Wv     = (const float*)d_in[5];
    const float* bv     = (const float*)d_in[6];
    const float* Wo     = (const float*)d_in[7];
    const float* bo     = (const float*)d_in[8];
    const float* slopes = (const float*)d_in[9];
    float* out = (float*)d_out;

    dim3 g1(24, 32);                 // fused QKV
    gemm_tc<<<g1, 128>>>(x, Wq, Wk, Wv, bq, bk, bv, nullptr, 0);

    dim3 g2(Ss / 128, Bb * Hh);      // 16 q-tiles x 32 (b,h)
    attn_tc<<<g2, 256>>>(slopes);

    dim3 g3(8, 32);                  // O projection
    gemm_tc<<<g3, 128>>>(nullptr, Wo, nullptr, nullptr, bo, nullptr, nullptr, out, 1);
}

// round 12
// speedup vs baseline: 3.0559x; 1.0249x over previous
#include <cuda_runtime.h>
#include <math.h>
#include <stdint.h>

#define Bb 2
#define Ss 2048
#define Dd 1024
#define Hh 16
#define DHh 64
#define MM (Bb*Ss)

// Scratch (device globals). Plain [M][D] layout.
__device__ float g_q[MM*Dd];
__device__ float g_k[MM*Dd];
__device__ float g_v[MM*Dd];
__device__ float g_att[MM*Dd];

__device__ __forceinline__ uint32_t f2tf(float f) {
    uint32_t u;
    asm("cvt.rna.tf32.f32 %0, %1;" : "=r"(u) : "f"(f));
    return u;
}

__device__ __forceinline__ void mma_tf32(float* c,
                                         const uint32_t* a,
                                         uint32_t b0, uint32_t b1) {
    asm volatile("mma.sync.aligned.m16n8k8.row.col.f32.tf32.tf32.f32 "
        "{%0,%1,%2,%3}, {%4,%5,%6,%7}, {%8,%9}, {%0,%1,%2,%3};"
        : "+f"(c[0]), "+f"(c[1]), "+f"(c[2]), "+f"(c[3])
        : "r"(a[0]), "r"(a[1]), "r"(a[2]), "r"(a[3]), "r"(b0), "r"(b1));
}

// ---------------------------------------------------------------------------
// tf32 GEMM: block 128x128, BK=16, 4 warps, warp tile 64x64 (unchanged).
// ---------------------------------------------------------------------------
__global__ __launch_bounds__(128, 2) void gemm_tc(
    const float* __restrict__ X,
    const float* __restrict__ W0, const float* __restrict__ W1, const float* __restrict__ W2,
    const float* __restrict__ b0p, const float* __restrict__ b1p, const float* __restrict__ b2p,
    float* __restrict__ OUTP, int mode)
{
    __shared__ uint32_t As[2][128][20];
    __shared__ uint32_t Bs[2][16][136];

    const float* A;
    const float* W;
    const float* bias;
    float* OUT;
    int n0;
    if (mode == 0) {
        const int sel = blockIdx.x >> 3;
        A = X;
        W    = (sel == 0) ? W0 : (sel == 1) ? W1 : W2;
        bias = (sel == 0) ? b0p : (sel == 1) ? b1p : b2p;
        OUT  = (sel == 0) ? g_q : (sel == 1) ? g_k : g_v;
        n0 = (blockIdx.x & 7) * 128;
    } else {
        A = g_att; W = W0; bias = b0p; OUT = OUTP;
        n0 = blockIdx.x * 128;
    }
    const int m0 = blockIdx.y * 128;
    const int tid  = threadIdx.x;
    const int lane = tid & 31;
    const int warp = tid >> 5;
    const int wm = warp & 1;
    const int wn = warp >> 1;
    const int lr = lane >> 2;
    const int lc = lane & 3;

    float c[4][8][4];
    #pragma unroll
    for (int mi = 0; mi < 4; mi++)
        #pragma unroll
        for (int ni = 0; ni < 8; ni++)
            #pragma unroll
            for (int q = 0; q < 4; q++) c[mi][ni][q] = 0.f;

    const int ar  = tid >> 2;
    const int ac4 = tid & 3;
    const int bkr = tid >> 5;
    const int bn4 = tid & 31;

    float4 av[4], bv[4];
    #pragma unroll
    for (int u = 0; u < 4; u++) {
        av[u] = *(const float4*)&A[(size_t)(m0 + ar + 32*u) * Dd + 4*ac4];
        bv[u] = *(const float4*)&W[(size_t)(bkr + 4*u) * Dd + n0 + 4*bn4];
    }
    #pragma unroll
    for (int u = 0; u < 4; u++) {
        *(uint4*)&As[0][ar + 32*u][4*ac4] =
            make_uint4(f2tf(av[u].x), f2tf(av[u].y), f2tf(av[u].z), f2tf(av[u].w));
        *(uint4*)&Bs[0][bkr + 4*u][4*bn4] =
            make_uint4(f2tf(bv[u].x), f2tf(bv[u].y), f2tf(bv[u].z), f2tf(bv[u].w));
    }
    __syncthreads();

    int buf = 0;
    for (int kt = 0; kt < 64; kt++) {
        const int kn = (kt + 1) * 16;
        if (kt < 63) {
            #pragma unroll
            for (int u = 0; u < 4; u++) {
                av[u] = *(const float4*)&A[(size_t)(m0 + ar + 32*u) * Dd + kn + 4*ac4];
                bv[u] = *(const float4*)&W[(size_t)(kn + bkr + 4*u) * Dd + n0 + 4*bn4];
            }
        }
        #pragma unroll
        for (int kc = 0; kc < 2; kc++) {
            uint32_t af[4][4], bf[8][2];
            #pragma unroll
            for (int mi = 0; mi < 4; mi++) {
                const int m = wm*64 + mi*16 + lr;
                af[mi][0] = As[buf][m][kc*8 + lc];
                af[mi][1] = As[buf][m + 8][kc*8 + lc];
                af[mi][2] = As[buf][m][kc*8 + lc + 4];
                af[mi][3] = As[buf][m + 8][kc*8 + lc + 4];
            }
            #pragma unroll
            for (int ni = 0; ni < 8; ni++) {
                const int n = wn*64 + ni*8 + lr;
                bf[ni][0] = Bs[buf][kc*8 + lc][n];
                bf[ni][1] = Bs[buf][kc*8 + lc + 4][n];
            }
            #pragma unroll
            for (int mi = 0; mi < 4; mi++)
                #pragma unroll
                for (int ni = 0; ni < 8; ni++)
                    mma_tf32(c[mi][ni], af[mi], bf[ni][0], bf[ni][1]);
        }
        if (kt < 63) {
            const int nb = buf ^ 1;
            #pragma unroll
            for (int u = 0; u < 4; u++) {
                *(uint4*)&As[nb][ar + 32*u][4*ac4] =
                    make_uint4(f2tf(av[u].x), f2tf(av[u].y), f2tf(av[u].z), f2tf(av[u].w));
                *(uint4*)&Bs[nb][bkr + 4*u][4*bn4] =
                    make_uint4(f2tf(bv[u].x), f2tf(bv[u].y), f2tf(bv[u].z), f2tf(bv[u].w));
            }
        }
        __syncthreads();
        buf ^= 1;
    }

    #pragma unroll
    for (int mi = 0; mi < 4; mi++) {
        const int row = m0 + wm*64 + mi*16 + lr;
        #pragma unroll
        for (int ni = 0; ni < 8; ni++) {
            const int col = n0 + wn*64 + ni*8 + 2*lc;
            const float bx = bias[col], by = bias[col + 1];
            *(float2*)&OUT[(size_t)row * Dd + col] =
                make_float2(c[mi][ni][0] + bx, c[mi][ni][1] + by);
            *(float2*)&OUT[(size_t)(row + 8) * Dd + col] =
                make_float2(c[mi][ni][2] + bx, c[mi][ni][3] + by);
        }
    }
}

// ---------------------------------------------------------------------------
// Flash attention v3: 64-q blocks, 128 threads (2 q-groups x 2 key-halves),
// 2 CTAs/SM. Per-half online softmax (no per-iter cross-warp exchange);
// halves merged once at the end. K stored pair-interleaved -> LDS.64 frags.
// ---------------------------------------------------------------------------
__global__ __launch_bounds__(128, 2) void attn_tc(const float* __restrict__ slopes)
{
    __shared__ __align__(16) uint32_t Ks[64*72];  // K (pair-interleaved cols)
    __shared__ __align__(16) uint32_t Vs[64*72];  // V [key][d]

    const int tid  = threadIdx.x;
    const int lane = tid & 31;
    const int warp = tid >> 5;
    const int qw = warp >> 1;      // 0..1 : q group (32 rows)
    const int kh = warp & 1;       // 0..1 : key half (32 keys)
    const int lr = lane >> 2;
    const int lc = lane & 3;
    const int b  = blockIdx.y >> 4;
    const int h  = blockIdx.y & (Hh - 1);
    const int q0 = blockIdx.x * 64;

    const float sp = log1pf(expf(slopes[h]));
    const unsigned FULL = 0xffffffffu;

    // Persistent Q fragments (rows qw*32 + mi*16 + lr(+8)), scale 1/8 folded.
    uint32_t qf[2][8][4];
    {
        const size_t rq = (size_t)(b*Ss + q0 + qw*32 + lr) * Dd + h*DHh;
        #pragma unroll
        for (int mi = 0; mi < 2; mi++) {
            const size_t r0 = rq + (size_t)(mi*16) * Dd;
            const size_t r1 = r0 + (size_t)8 * Dd;
            #pragma unroll
            for (int kc = 0; kc < 8; kc++) {
                const int cc = kc*8 + lc;
                qf[mi][kc][0] = f2tf(0.125f * g_q[r0 + cc]);
                qf[mi][kc][1] = f2tf(0.125f * g_q[r1 + cc]);
                qf[mi][kc][2] = f2tf(0.125f * g_q[r0 + cc + 4]);
                qf[mi][kc][3] = f2tf(0.125f * g_q[r1 + cc + 4]);
            }
        }
    }

    float o[2][8][4];
    #pragma unroll
    for (int mi = 0; mi < 2; mi++)
        #pragma unroll
        for (int nd = 0; nd < 8; nd++)
            #pragma unroll
            for (int q = 0; q < 4; q++) o[mi][nd][q] = 0.f;

    float m_r[2][2], l_r[2][2];
    #pragma unroll
    for (int mi = 0; mi < 2; mi++)
        #pragma unroll
        for (int rh = 0; rh < 2; rh++) { m_r[mi][rh] = -1e30f; l_r[mi][rh] = 0.f; }

    const float qr_base = (float)(q0 + qw*32 + lr);

    for (int t = 0; t < Ss/64; t++) {
        const int k0 = t * 64;
        __syncthreads();
        // K tile: pair-interleave cols within each 8-group: c -> 2(c&3)+(c>>2)
        #pragma unroll
        for (int i = 0; i < 4; i++) {
            const int idx = tid + i*128;          // 0..511
            const int key = idx >> 3;
            const int g8  = (idx & 7) * 8;
            const size_t g = (size_t)(b*Ss + k0 + key) * Dd + h*DHh + g8;
            float4 f0 = *(const float4*)&g_k[g];
            float4 f1 = *(const float4*)&g_k[g + 4];
            *(uint4*)&Ks[key*72 + g8] =
                make_uint4(f2tf(f0.x), f2tf(f1.x), f2tf(f0.y), f2tf(f1.y));
            *(uint4*)&Ks[key*72 + g8 + 4] =
                make_uint4(f2tf(f0.z), f2tf(f1.z), f2tf(f0.w), f2tf(f1.w));
        }
        // V tile: plain
        #pragma unroll
        for (int i = 0; i < 8; i++) {
            const int idx = tid + i*128;          // 0..1023
            const int key = idx >> 4;
            const int c4  = (idx & 15) * 4;
            const size_t g = (size_t)(b*Ss + k0 + key) * Dd + h*DHh + c4;
            float4 v = *(const float4*)&g_v[g];
            *(uint4*)&Vs[key*72 + c4] =
                make_uint4(f2tf(v.x), f2tf(v.y), f2tf(v.z), f2tf(v.w));
        }
        __syncthreads();

        // S = Q K^T  (warp: 32q x 32key of its half)
        float sc[2][4][4];
        #pragma unroll
        for (int mi = 0; mi < 2; mi++)
            #pragma unroll
            for (int ni = 0; ni < 4; ni++)
                #pragma unroll
                for (int q = 0; q < 4; q++) sc[mi][ni][q] = 0.f;
        #pragma unroll
        for (int kc = 0; kc < 8; kc++) {
            uint2 kb[4];
            #pragma unroll
            for (int ni = 0; ni < 4; ni++) {
                const int key = kh*32 + ni*8 + lr;
                kb[ni] = *(const uint2*)&Ks[key*72 + kc*8 + 2*lc];
            }
            #pragma unroll
            for (int mi = 0; mi < 2; mi++)
                #pragma unroll
                for (int ni = 0; ni < 4; ni++)
                    mma_tf32(sc[mi][ni], qf[mi][kc], kb[ni].x, kb[ni].y);
        }

        // ALiBi bias + per-half online softmax (warp-local only)
        float scl[2][2];
        #pragma unroll
        for (int mi = 0; mi < 2; mi++) {
            const float qr0 = qr_base + (float)(mi*16);
            const float qr1 = qr0 + 8.f;
            float p0 = -1e30f, p1 = -1e30f;
            #pragma unroll
            for (int ni = 0; ni < 4; ni++) {
                const float kp = (float)(k0 + kh*32 + ni*8 + 2*lc);
                sc[mi][ni][0] = fmaf(-sp, fabsf(qr0 - kp),       sc[mi][ni][0]);
                sc[mi][ni][1] = fmaf(-sp, fabsf(qr0 - (kp+1.f)), sc[mi][ni][1]);
                sc[mi][ni][2] = fmaf(-sp, fabsf(qr1 - kp),       sc[mi][ni][2]);
                sc[mi][ni][3] = fmaf(-sp, fabsf(qr1 - (kp+1.f)), sc[mi][ni][3]);
                p0 = fmaxf(p0, fmaxf(sc[mi][ni][0], sc[mi][ni][1]));
                p1 = fmaxf(p1, fmaxf(sc[mi][ni][2], sc[mi][ni][3]));
            }
            p0 = fmaxf(p0, __shfl_xor_sync(FULL, p0, 1));
            p0 = fmaxf(p0, __shfl_xor_sync(FULL, p0, 2));
            p1 = fmaxf(p1, __shfl_xor_sync(FULL, p1, 1));
            p1 = fmaxf(p1, __shfl_xor_sync(FULL, p1, 2));
            const float mn0 = fmaxf(m_r[mi][0], p0);
            const float mn1 = fmaxf(m_r[mi][1], p1);
            scl[mi][0] = __expf(m_r[mi][0] - mn0);
            scl[mi][1] = __expf(m_r[mi][1] - mn1);
            m_r[mi][0] = mn0; m_r[mi][1] = mn1;
            float s0 = 0.f, s1 = 0.f;
            #pragma unroll
            for (int ni = 0; ni < 4; ni++) {
                sc[mi][ni][0] = __expf(sc[mi][ni][0] - mn0);
                sc[mi][ni][1] = __expf(sc[mi][ni][1] - mn0);
                sc[mi][ni][2] = __expf(sc[mi][ni][2] - mn1);
                sc[mi][ni][3] = __expf(sc[mi][ni][3] - mn1);
                s0 += sc[mi][ni][0] + sc[mi][ni][1];
                s1 += sc[mi][ni][2] + sc[mi][ni][3];
            }
            s0 += __shfl_xor_sync(FULL, s0, 1);
            s0 += __shfl_xor_sync(FULL, s0, 2);
            s1 += __shfl_xor_sync(FULL, s1, 1);
            s1 += __shfl_xor_sync(FULL, s1, 2);
            l_r[mi][0] = l_r[mi][0] * scl[mi][0] + s0;
            l_r[mi][1] = l_r[mi][1] * scl[mi][1] + s1;
        }

        // Rescale O, transform P (C-frag -> A-frag via quad shuffles), PV
        #pragma unroll
        for (int mi = 0; mi < 2; mi++)
            #pragma unroll
            for (int nd = 0; nd < 8; nd++) {
                o[mi][nd][0] *= scl[mi][0]; o[mi][nd][1] *= scl[mi][0];
                o[mi][nd][2] *= scl[mi][1]; o[mi][nd][3] *= scl[mi][1];
            }
        const int s0l = (lane & 28) + (lc >> 1);
        const int s1l = s0l + 2;
        const bool odd = (lc & 1);
        #pragma unroll
        for (int ni = 0; ni < 4; ni++) {
            uint32_t pa[2][4];
            #pragma unroll
            for (int mi = 0; mi < 2; mi++) {
                float x0 = __shfl_sync(FULL, sc[mi][ni][0], s0l);
                float x1 = __shfl_sync(FULL, sc[mi][ni][1], s0l);
                float y0 = __shfl_sync(FULL, sc[mi][ni][2], s0l);
                float y1 = __shfl_sync(FULL, sc[mi][ni][3], s0l);
                float z0 = __shfl_sync(FULL, sc[mi][ni][0], s1l);
                float z1 = __shfl_sync(FULL, sc[mi][ni][1], s1l);
                float w0 = __shfl_sync(FULL, sc[mi][ni][2], s1l);
                float w1 = __shfl_sync(FULL, sc[mi][ni][3], s1l);
                pa[mi][0] = f2tf(odd ? x1 : x0);
                pa[mi][1] = f2tf(odd ? y1 : y0);
                pa[mi][2] = f2tf(odd ? z1 : z0);
                pa[mi][3] = f2tf(odd ? w1 : w0);
            }
            const int krow0 = (kh*32 + ni*8 + lc) * 72;
            const int krow1 = krow0 + 4*72;
            #pragma unroll
            for (int nd = 0; nd < 8; nd++) {
                const uint32_t b0 = Vs[krow0 + nd*8 + lr];
                const uint32_t b1 = Vs[krow1 + nd*8 + lr];
                mma_tf32(o[0][nd], pa[0], b0, b1);
                mma_tf32(o[1][nd], pa[1], b0, b1);
            }
        }
    }

    // Merge the two key-half partials (different m,l) through reused smem.
    __syncthreads();
    float* Ob = (float*)Ks;   // rows [64] x 68 floats: 64 O cols + m at 64, l at 65
    if (kh == 0) {
        #pragma unroll
        for (int mi = 0; mi < 2; mi++) {
            const int r0 = qw*32 + mi*16 + lr;
            #pragma unroll
            for (int nd = 0; nd < 8; nd++) {
                const int cc = nd*8 + 2*lc;
                *(float2*)&Ob[r0*68 + cc]     = make_float2(o[mi][nd][0], o[mi][nd][1]);
                *(float2*)&Ob[(r0+8)*68 + cc] = make_float2(o[mi][nd][2], o[mi][nd][3]);
            }
            if (lc == 0) {
                Ob[r0*68 + 64]     = m_r[mi][0];
                Ob[r0*68 + 65]     = l_r[mi][0];
                Ob[(r0+8)*68 + 64] = m_r[mi][1];
                Ob[(r0+8)*68 + 65] = l_r[mi][1];
            }
        }
    }
    __syncthreads();
    if (kh == 1) {
        #pragma unroll
        for (int mi = 0; mi < 2; mi++) {
            float A0[2], A1[2];
            #pragma unroll
            for (int rh = 0; rh < 2; rh++) {
                const int row = qw*32 + mi*16 + rh*8 + lr;
                const float m0 = Ob[row*68 + 64];
                const float l0 = Ob[row*68 + 65];
                const float m1 = m_r[mi][rh];
                const float mm = fmaxf(m0, m1);
                const float e0 = __expf(m0 - mm);
                const float e1 = __expf(m1 - mm);
                const float inv = 1.f / (l0*e0 + l_r[mi][rh]*e1);
                A0[rh] = e0 * inv;
                A1[rh] = e1 * inv;
            }
            const int r0 = qw*32 + mi*16 + lr;
            const size_t g0 = (size_t)(b*Ss + q0 + r0) * Dd + h*DHh;
            const size_t g1 = g0 + (size_t)8 * Dd;
            #pragma unroll
            for (int nd = 0; nd < 8; nd++) {
                const int cc = nd*8 + 2*lc;
                float2 p0 = *(float2*)&Ob[r0*68 + cc];
                float2 p1 = *(float2*)&Ob[(r0+8)*68 + cc];
                *(float2*)&g_att[g0 + cc] =
                    make_float2(p0.x*A0[0] + o[mi][nd][0]*A1[0],
                                p0.y*A0[0] + o[mi][nd][1]*A1[0]);
                *(float2*)&g_att[g1 + cc] =
                    make_float2(p1.x*A0[1] + o[mi][nd][2]*A1[1],
                                p1.y*A0[1] + o[mi][nd][3]*A1[1]);
            }
        }
    }
}

extern "C" void kernel_launch(void* const* d_in, const int* in_sizes, int n_in,
                              void* d_out, int out_size)
{
    const float* x      = (const float*)d_in[0];
    const float* Wq     = (const float*)d_in[1];
    const float* bq     = (const float*)d_in[2];
    const float* Wk     = (const float*)d_in[3];
    const float* bk     = (const float*)d_in[4];
    const float* Wv     = (const float*)d_in[5];
    const float* bv     = (const float*)d_in[6];
    const float* Wo     = (const float*)d_in[7];
    const float* bo     = (const float*)d_in[8];
    const float* slopes = (const float*)d_in[9];
    float* out = (float*)d_out;

    dim3 g1(24, 32);                 // fused QKV
    gemm_tc<<<g1, 128>>>(x, Wq, Wk, Wv, bq, bk, bv, nullptr, 0);

    dim3 g2(Ss / 64, Bb * Hh);       // 32 q-tiles x 32 (b,h)
    attn_tc<<<g2, 128>>>(slopes);

    dim3 g3(8, 32);                  // O projection
    gemm_tc<<<g3, 128>>>(nullptr, Wo, nullptr, nullptr, bo, nullptr, nullptr, out, 1);
}

// round 14
// speedup vs baseline: 3.5549x; 1.1633x over previous
#include <cuda_runtime.h>
#include <math.h>
#include <stdint.h>

#define Bb 2
#define Ss 2048
#define Dd 1024
#define Hh 16
#define DHh 64
#define MM (Bb*Ss)

// Scratch (device globals). tf32-bit payloads stored as uint32.
__device__ uint32_t g_xt[MM*Dd];
__device__ uint32_t g_wt[4][Dd*Dd];     // Wq, Wk, Wv, Wo (tf32)
__device__ uint32_t g_q[MM*Dd];         // tf32, 0.125 folded
__device__ uint32_t g_k[MM*Dd];         // tf32
__device__ uint32_t g_v[MM*Dd];         // tf32
__device__ uint32_t g_att[MM*Dd];       // tf32

__device__ __forceinline__ uint32_t f2tf(float f) {
    uint32_t u;
    asm("cvt.rna.tf32.f32 %0, %1;" : "=r"(u) : "f"(f));
    return u;
}

__device__ __forceinline__ void mma_tf32(float* c,
                                         const uint32_t* a,
                                         uint32_t b0, uint32_t b1) {
    asm volatile("mma.sync.aligned.m16n8k8.row.col.f32.tf32.tf32.f32 "
        "{%0,%1,%2,%3}, {%4,%5,%6,%7}, {%8,%9}, {%0,%1,%2,%3};"
        : "+f"(c[0]), "+f"(c[1]), "+f"(c[2]), "+f"(c[3])
        : "r"(a[0]), "r"(a[1]), "r"(a[2]), "r"(a[3]), "r"(b0), "r"(b1));
}

__device__ __forceinline__ void cpa16(uint32_t dst, const void* src) {
    asm volatile("cp.async.cg.shared.global [%0], [%1], 16;\n" :: "r"(dst), "l"(src));
}
__device__ __forceinline__ void cp_commit() {
    asm volatile("cp.async.commit_group;\n" ::);
}
template<int N> __device__ __forceinline__ void cp_wait() {
    asm volatile("cp.async.wait_group %0;\n" :: "n"(N));
}

// ---------------------------------------------------------------------------
// Pre-convert fp32 -> tf32 bits. which: 0=X->g_xt, 1..4 -> g_wt[0..3]
// ---------------------------------------------------------------------------
__global__ __launch_bounds__(256) void cvt_tf32(const float4* __restrict__ src,
                                                int which, int n4)
{
    const int i = blockIdx.x * blockDim.x + threadIdx.x;
    if (i >= n4) return;
    uint4* dst = (which == 0) ? (uint4*)g_xt : (uint4*)g_wt[which - 1];
    float4 v = src[i];
    dst[i] = make_uint4(f2tf(v.x), f2tf(v.y), f2tf(v.z), f2tf(v.w));
}

// ---------------------------------------------------------------------------
// tf32 GEMM, 3-stage cp.async pipeline. Operands pre-converted in gmem.
// Block 128x128, BK=16, 4 warps (64x64 warp tiles).
// mode 0: grid(24,32) fused QKV -> g_q/g_k/g_v (tf32 out, Q scaled 0.125)
// mode 1: grid(8,32)  g_att x Wo -> fp32 OUTP
// Dynamic smem: 3*(128*20 + 16*136)*4 = 56832 B.
// ---------------------------------------------------------------------------
__global__ __launch_bounds__(128, 2) void gemm_tc(float* __restrict__ OUTP, int mode)
{
    extern __shared__ uint32_t smem[];
    const uint32_t smaddr = (uint32_t)__cvta_generic_to_shared(smem);

    const uint32_t* A;
    const uint32_t* W;
    int sel, n0;
    if (mode == 0) {
        sel = blockIdx.x >> 3;
        A = g_xt;
        W = g_wt[sel];
        n0 = (blockIdx.x & 7) * 128;
    } else {
        sel = 3;
        A = g_att;
        W = g_wt[3];
        n0 = blockIdx.x * 128;
    }
    const int m0 = blockIdx.y * 128;
    const int tid  = threadIdx.x;
    const int lane = tid & 31;
    const int warp = tid >> 5;
    const int wm = warp & 1;
    const int wn = warp >> 1;
    const int lr = lane >> 2;
    const int lc = lane & 3;

    float c[4][8][4];
    #pragma unroll
    for (int mi = 0; mi < 4; mi++)
        #pragma unroll
        for (int ni = 0; ni < 8; ni++)
            #pragma unroll
            for (int q = 0; q < 4; q++) c[mi][ni][q] = 0.f;

    const int ar  = tid >> 2;   // A rows ar + 32u
    const int ac4 = tid & 3;    // 16B chunk within 16-k tile
    const int bkr = tid >> 5;   // B k-rows bkr + 4u
    const int bn4 = tid & 31;   // 16B chunk within 128-n tile

    // stage layout: As[st] at st*2560 words, Bs[st] at 7680 + st*2176 words
    #define LOAD_STAGE(st, kk) do {                                             \
        const uint32_t ab = smaddr + (uint32_t)(st)*2560*4;                     \
        const uint32_t bb = smaddr + (7680u + (uint32_t)(st)*2176u)*4;          \
        _Pragma("unroll")                                                       \
        for (int u = 0; u < 4; u++) {                                           \
            cpa16(ab + (uint32_t)((ar + 32*u)*20 + 4*ac4)*4,                    \
                  &A[(size_t)(m0 + ar + 32*u) * Dd + (kk) + 4*ac4]);            \
            cpa16(bb + (uint32_t)((bkr + 4*u)*136 + 4*bn4)*4,                   \
                  &W[(size_t)((kk) + bkr + 4*u) * Dd + n0 + 4*bn4]);            \
        }                                                                       \
    } while (0)

    LOAD_STAGE(0, 0);  cp_commit();
    LOAD_STAGE(1, 16); cp_commit();

    for (int kt = 0; kt < 64; kt++) {
        if (kt < 63) cp_wait<1>(); else cp_wait<0>();
        __syncthreads();
        if (kt < 62) {
            const int st = (kt + 2) % 3;
            LOAD_STAGE(st, (kt + 2) * 16);
            cp_commit();
        }
        const int buf = kt % 3;
        const uint32_t* as = smem + buf * 2560;
        const uint32_t* bs = smem + 7680 + buf * 2176;
        #pragma unroll
        for (int kc = 0; kc < 2; kc++) {
            uint32_t af[4][4], bf[8][2];
            #pragma unroll
            for (int mi = 0; mi < 4; mi++) {
                const int m = wm*64 + mi*16 + lr;
                af[mi][0] = as[m*20 + kc*8 + lc];
                af[mi][1] = as[(m + 8)*20 + kc*8 + lc];
                af[mi][2] = as[m*20 + kc*8 + lc + 4];
                af[mi][3] = as[(m + 8)*20 + kc*8 + lc + 4];
            }
            #pragma unroll
            for (int ni = 0; ni < 8; ni++) {
                const int n = wn*64 + ni*8 + lr;
                bf[ni][0] = bs[(kc*8 + lc)*136 + n];
                bf[ni][1] = bs[(kc*8 + lc + 4)*136 + n];
            }
            #pragma unroll
            for (int mi = 0; mi < 4; mi++)
                #pragma unroll
                for (int ni = 0; ni < 8; ni++)
                    mma_tf32(c[mi][ni], af[mi], bf[ni][0], bf[ni][1]);
        }
    }
    #undef LOAD_STAGE

    if (mode == 0) {
        uint32_t* OUTU = (sel == 0) ? g_q : (sel == 1) ? g_k : g_v;
        const float* bias = nullptr;   // biases are zero-extended below via cbias
        // biases passed through constant path: reconstruct from param-free globals
        // (all biases are inputs; fetched in launch wrapper via OUTP==nullptr trick
        //  not needed: we read bias from gmem pointer table) -- see kernel_launch:
        // bias pointers are stashed in g_bias_ptrs.
        extern __device__ const float* g_bias_ptrs[4];
        bias = g_bias_ptrs[sel];
        const float qs = (sel == 0) ? 0.125f : 1.0f;
        #pragma unroll
        for (int mi = 0; mi < 4; mi++) {
            const int row = m0 + wm*64 + mi*16 + lr;
            #pragma unroll
            for (int ni = 0; ni < 8; ni++) {
                const int col = n0 + wn*64 + ni*8 + 2*lc;
                const float bx = bias[col], by = bias[col + 1];
                *(uint2*)&OUTU[(size_t)row * Dd + col] =
                    make_uint2(f2tf((c[mi][ni][0] + bx) * qs),
                               f2tf((c[mi][ni][1] + by) * qs));
                *(uint2*)&OUTU[(size_t)(row + 8) * Dd + col] =
                    make_uint2(f2tf((c[mi][ni][2] + bx) * qs),
                               f2tf((c[mi][ni][3] + by) * qs));
            }
        }
    } else {
        extern __device__ const float* g_bias_ptrs[4];
        const float* bias = g_bias_ptrs[3];
        #pragma unroll
        for (int mi = 0; mi < 4; mi++) {
            const int row = m0 + wm*64 + mi*16 + lr;
            #pragma unroll
            for (int ni = 0; ni < 8; ni++) {
                const int col = n0 + wn*64 + ni*8 + 2*lc;
                const float bx = bias[col], by = bias[col + 1];
                *(float2*)&OUTP[(size_t)row * Dd + col] =
                    make_float2(c[mi][ni][0] + bx, c[mi][ni][1] + by);
                *(float2*)&OUTP[(size_t)(row + 8) * Dd + col] =
                    make_float2(c[mi][ni][2] + bx, c[mi][ni][3] + by);
            }
        }
    }
}

__device__ const float* g_bias_ptrs[4];
__global__ void set_bias_ptrs(const float* bq, const float* bk,
                              const float* bv, const float* bo) {
    g_bias_ptrs[0] = bq; g_bias_ptrs[1] = bk;
    g_bias_ptrs[2] = bv; g_bias_ptrs[3] = bo;
}

// ---------------------------------------------------------------------------
// Flash attention: 64-q blocks, 128 threads (2 q-groups x 2 key-halves),
// per-half online softmax, end merge. K/V pre-tf32 in gmem, double-buffered
// cp.async pipeline (2 stages). K stride 68, V stride 72 (conflict-free).
// Dynamic smem: (2*64*68 + 2*64*72)*4 = 71680 B.
// ---------------------------------------------------------------------------
__global__ __launch_bounds__(128, 2) void attn_tc(const float* __restrict__ slopes)
{
    extern __shared__ uint32_t smem[];
    const uint32_t smaddr = (uint32_t)__cvta_generic_to_shared(smem);
    // Ks[st]: st*4352 words ; Vs[st]: 8704 + st*4608 words

    const int tid  = threadIdx.x;
    const int lane = tid & 31;
    const int warp = tid >> 5;
    const int qw = warp >> 1;
    const int kh = warp & 1;
    const int lr = lane >> 2;
    const int lc = lane & 3;
    const int b  = blockIdx.y >> 4;
    const int h  = blockIdx.y & (Hh - 1);
    const int q0 = blockIdx.x * 64;

    const float sp = log1pf(expf(slopes[h]));
    const unsigned FULL = 0xffffffffu;

    // Persistent Q fragments (already tf32, 0.125 folded)
    uint32_t qf[2][8][4];
    {
        const size_t rq = (size_t)(b*Ss + q0 + qw*32 + lr) * Dd + h*DHh;
        #pragma unroll
        for (int mi = 0; mi < 2; mi++) {
            const size_t r0 = rq + (size_t)(mi*16) * Dd;
            const size_t r1 = r0 + (size_t)8 * Dd;
            #pragma unroll
            for (int kc = 0; kc < 8; kc++) {
                const int cc = kc*8 + lc;
                qf[mi][kc][0] = g_q[r0 + cc];
                qf[mi][kc][1] = g_q[r1 + cc];
                qf[mi][kc][2] = g_q[r0 + cc + 4];
                qf[mi][kc][3] = g_q[r1 + cc + 4];
            }
        }
    }

    float o[2][8][4];
    #pragma unroll
    for (int mi = 0; mi < 2; mi++)
        #pragma unroll
        for (int nd = 0; nd < 8; nd++)
            #pragma unroll
            for (int q = 0; q < 4; q++) o[mi][nd][q] = 0.f;

    float m_r[2][2], l_r[2][2];
    #pragma unroll
    for (int mi = 0; mi < 2; mi++)
        #pragma unroll
        for (int rh = 0; rh < 2; rh++) { m_r[mi][rh] = -1e30f; l_r[mi][rh] = 0.f; }

    const float qr_base = (float)(q0 + qw*32 + lr);

    #define LOAD_KV(st, k0v) do {                                               \
        const uint32_t kb_ = smaddr + (uint32_t)(st)*4352u*4;                   \
        const uint32_t vb_ = smaddr + (8704u + (uint32_t)(st)*4608u)*4;         \
        _Pragma("unroll")                                                       \
        for (int i_ = 0; i_ < 8; i_++) {                                        \
            const int c_  = tid + i_*128;                                       \
            const int key = c_ >> 4;                                            \
            const int c4  = (c_ & 15) * 4;                                      \
            const size_t g_ = (size_t)(b*Ss + (k0v) + key)*Dd + h*DHh + c4;     \
            cpa16(kb_ + (uint32_t)(key*68 + c4)*4, &g_k[g_]);                   \
            cpa16(vb_ + (uint32_t)(key*72 + c4)*4, &g_v[g_]);                   \
        }                                                                       \
    } while (0)

    LOAD_KV(0, 0); cp_commit();

    for (int t = 0; t < Ss/64; t++) {
        const int k0 = t * 64;
        __syncthreads();                     // all warps done with buf (t-1)&1
        if (t + 1 < Ss/64) {
            LOAD_KV((t + 1) & 1, k0 + 64);
            cp_commit();
            cp_wait<1>();                    // stage t complete
        } else {
            cp_wait<0>();
        }
        __syncthreads();

        const uint32_t* ks = smem + (t & 1) * 4352;
        const uint32_t* vs = smem + 8704 + (t & 1) * 4608;

        // S = Q K^T  (warp: 32q x 32key of its half)
        float sc[2][4][4];
        #pragma unroll
        for (int mi = 0; mi < 2; mi++)
            #pragma unroll
            for (int ni = 0; ni < 4; ni++)
                #pragma unroll
                for (int q = 0; q < 4; q++) sc[mi][ni][q] = 0.f;
        #pragma unroll
        for (int kc = 0; kc < 8; kc++) {
            uint32_t kb0[4], kb1[4];
            #pragma unroll
            for (int ni = 0; ni < 4; ni++) {
                const uint32_t* kr = ks + (kh*32 + ni*8 + lr)*68 + kc*8 + lc;
                kb0[ni] = kr[0];
                kb1[ni] = kr[4];
            }
            #pragma unroll
            for (int mi = 0; mi < 2; mi++)
                #pragma unroll
                for (int ni = 0; ni < 4; ni++)
                    mma_tf32(sc[mi][ni], qf[mi][kc], kb0[ni], kb1[ni]);
        }

        // ALiBi bias + per-half online softmax
        float scl[2][2];
        #pragma unroll
        for (int mi = 0; mi < 2; mi++) {
            const float qr0 = qr_base + (float)(mi*16);
            const float qr1 = qr0 + 8.f;
            float p0 = -1e30f, p1 = -1e30f;
            #pragma unroll
            for (int ni = 0; ni < 4; ni++) {
                const float kp = (float)(k0 + kh*32 + ni*8 + 2*lc);
                sc[mi][ni][0] = fmaf(-sp, fabsf(qr0 - kp),       sc[mi][ni][0]);
                sc[mi][ni][1] = fmaf(-sp, fabsf(qr0 - (kp+1.f)), sc[mi][ni][1]);
                sc[mi][ni][2] = fmaf(-sp, fabsf(qr1 - kp),       sc[mi][ni][2]);
                sc[mi][ni][3] = fmaf(-sp, fabsf(qr1 - (kp+1.f)), sc[mi][ni][3]);
                p0 = fmaxf(p0, fmaxf(sc[mi][ni][0], sc[mi][ni][1]));
                p1 = fmaxf(p1, fmaxf(sc[mi][ni][2], sc[mi][ni][3]));
            }
            p0 = fmaxf(p0, __shfl_xor_sync(FULL, p0, 1));
            p0 = fmaxf(p0, __shfl_xor_sync(FULL, p0, 2));
            p1 = fmaxf(p1, __shfl_xor_sync(FULL, p1, 1));
            p1 = fmaxf(p1, __shfl_xor_sync(FULL, p1, 2));
            const float mn0 = fmaxf(m_r[mi][0], p0);
            const float mn1 = fmaxf(m_r[mi][1], p1);
            scl[mi][0] = __expf(m_r[mi][0] - mn0);
            scl[mi][1] = __expf(m_r[mi][1] - mn1);
            m_r[mi][0] = mn0; m_r[mi][1] = mn1;
            float s0 = 0.f, s1 = 0.f;
            #pragma unroll
            for (int ni = 0; ni < 4; ni++) {
                sc[mi][ni][0] = __expf(sc[mi][ni][0] - mn0);
                sc[mi][ni][1] = __expf(sc[mi][ni][1] - mn0);
                sc[mi][ni][2] = __expf(sc[mi][ni][2] - mn1);
                sc[mi][ni][3] = __expf(sc[mi][ni][3] - mn1);
                s0 += sc[mi][ni][0] + sc[mi][ni][1];
                s1 += sc[mi][ni][2] + sc[mi][ni][3];
            }
            s0 += __shfl_xor_sync(FULL, s0, 1);
            s0 += __shfl_xor_sync(FULL, s0, 2);
            s1 += __shfl_xor_sync(FULL, s1, 1);
            s1 += __shfl_xor_sync(FULL, s1, 2);
            l_r[mi][0] = l_r[mi][0] * scl[mi][0] + s0;
            l_r[mi][1] = l_r[mi][1] * scl[mi][1] + s1;
        }

        // Rescale O, P C-frag -> A-frag via quad shuffles, PV accumulate
        #pragma unroll
        for (int mi = 0; mi < 2; mi++)
            #pragma unroll
            for (int nd = 0; nd < 8; nd++) {
                o[mi][nd][0] *= scl[mi][0]; o[mi][nd][1] *= scl[mi][0];
                o[mi][nd][2] *= scl[mi][1]; o[mi][nd][3] *= scl[mi][1];
            }
        const int s0l = (lane & 28) + (lc >> 1);
        const int s1l = s0l + 2;
        const bool odd = (lc & 1);
        #pragma unroll
        for (int ni = 0; ni < 4; ni++) {
            uint32_t pa[2][4];
            #pragma unroll
            for (int mi = 0; mi < 2; mi++) {
                float x0 = __shfl_sync(FULL, sc[mi][ni][0], s0l);
                float x1 = __shfl_sync(FULL, sc[mi][ni][1], s0l);
                float y0 = __shfl_sync(FULL, sc[mi][ni][2], s0l);
                float y1 = __shfl_sync(FULL, sc[mi][ni][3], s0l);
                float z0 = __shfl_sync(FULL, sc[mi][ni][0], s1l);
                float z1 = __shfl_sync(FULL, sc[mi][ni][1], s1l);
                float w0 = __shfl_sync(FULL, sc[mi][ni][2], s1l);
                float w1 = __shfl_sync(FULL, sc[mi][ni][3], s1l);
                pa[mi][0] = f2tf(odd ? x1 : x0);
                pa[mi][1] = f2tf(odd ? y1 : y0);
                pa[mi][2] = f2tf(odd ? z1 : z0);
                pa[mi][3] = f2tf(odd ? w1 : w0);
            }
            const uint32_t* vr0 = vs + (kh*32 + ni*8 + lc)*72;
            const uint32_t* vr1 = vr0 + 4*72;
            #pragma unroll
            for (int nd = 0; nd < 8; nd++) {
                const uint32_t b0 = vr0[nd*8 + lr];
                const uint32_t b1 = vr1[nd*8 + lr];
                mma_tf32(o[0][nd], pa[0], b0, b1);
                mma_tf32(o[1][nd], pa[1], b0, b1);
            }
        }
    }
    #undef LOAD_KV

    // Merge the two key-half partials through reused smem.
    __syncthreads();
    float* Ob = (float*)smem;   // [64] rows x 68 floats: 64 O cols, m@64, l@65
    if (kh == 0) {
        #pragma unroll
        for (int mi = 0; mi < 2; mi++) {
            const int r0 = qw*32 + mi*16 + lr;
            #pragma unroll
            for (int nd = 0; nd < 8; nd++) {
                const int cc = nd*8 + 2*lc;
                *(float2*)&Ob[r0*68 + cc]     = make_float2(o[mi][nd][0], o[mi][nd][1]);
                *(float2*)&Ob[(r0+8)*68 + cc] = make_float2(o[mi][nd][2], o[mi][nd][3]);
            }
            if (lc == 0) {
                Ob[r0*68 + 64]     = m_r[mi][0];
                Ob[r0*68 + 65]     = l_r[mi][0];
                Ob[(r0+8)*68 + 64] = m_r[mi][1];
                Ob[(r0+8)*68 + 65] = l_r[mi][1];
            }
        }
    }
    __syncthreads();
    if (kh == 1) {
        #pragma unroll
        for (int mi = 0; mi < 2; mi++) {
            float A0[2], A1[2];
            #pragma unroll
            for (int rh = 0; rh < 2; rh++) {
                const int row = qw*32 + mi*16 + rh*8 + lr;
                const float m0 = Ob[row*68 + 64];
                const float l0 = Ob[row*68 + 65];
                const float m1 = m_r[mi][rh];
                const float mm = fmaxf(m0, m1);
                const float e0 = __expf(m0 - mm);
                const float e1 = __expf(m1 - mm);
                const float inv = 1.f / (l0*e0 + l_r[mi][rh]*e1);
                A0[rh] = e0 * inv;
                A1[rh] = e1 * inv;
            }
            const int r0 = qw*32 + mi*16 + lr;
            const size_t g0 = (size_t)(b*Ss + q0 + r0) * Dd + h*DHh;
            const size_t g1 = g0 + (size_t)8 * Dd;
            #pragma unroll
            for (int nd = 0; nd < 8; nd++) {
                const int cc = nd*8 + 2*lc;
                float2 p0 = *(float2*)&Ob[r0*68 + cc];
                float2 p1 = *(float2*)&Ob[(r0+8)*68 + cc];
                *(uint2*)&g_att[g0 + cc] = make_uint2(
                    f2tf(p0.x*A0[0] + o[mi][nd][0]*A1[0]),
                    f2tf(p0.y*A0[0] + o[mi][nd][1]*A1[0]));
                *(uint2*)&g_att[g1 + cc] = make_uint2(
                    f2tf(p1.x*A0[1] + o[mi][nd][2]*A1[1]),
                    f2tf(p1.y*A0[1] + o[mi][nd][3]*A1[1]));
            }
        }
    }
}

extern "C" void kernel_launch(void* const* d_in, const int* in_sizes, int n_in,
                              void* d_out, int out_size)
{
    const float* x      = (const float*)d_in[0];
    const float* Wq     = (const float*)d_in[1];
    const float* bq     = (const float*)d_in[2];
    const float* Wk     = (const float*)d_in[3];
    const float* bk     = (const float*)d_in[4];
    const float* Wv     = (const float*)d_in[5];
    const float* bv     = (const float*)d_in[6];
    const float* Wo     = (const float*)d_in[7];
    const float* bo     = (const float*)d_in[8];
    const float* slopes = (const float*)d_in[9];
    float* out = (float*)d_out;

    static const int SMEM_G = 3 * (128*20 + 16*136) * 4;   // 56832
    static const int SMEM_A = 2 * (64*68 + 64*72) * 4;     // 71680
    cudaFuncSetAttribute(gemm_tc, cudaFuncAttributeMaxDynamicSharedMemorySize, SMEM_G);
    cudaFuncSetAttribute(attn_tc, cudaFuncAttributeMaxDynamicSharedMemorySize, SMEM_A);

    set_bias_ptrs<<<1, 1>>>(bq, bk, bv, bo);

    const int NX4 = MM*Dd/4;      // 1048576
    const int NW4 = Dd*Dd/4;      // 262144
    cvt_tf32<<<NX4/256, 256>>>((const float4*)x,  0, NX4);
    cvt_tf32<<<NW4/256, 256>>>((const float4*)Wq, 1, NW4);
    cvt_tf32<<<NW4/256, 256>>>((const float4*)Wk, 2, NW4);
    cvt_tf32<<<NW4/256, 256>>>((const float4*)Wv, 3, NW4);
    cvt_tf32<<<NW4/256, 256>>>((const float4*)Wo, 4, NW4);

    dim3 g1(24, 32);                 // fused QKV
    gemm_tc<<<g1, 128, SMEM_G>>>(nullptr, 0);

    dim3 g2(Ss / 64, Bb * Hh);       // attention
    attn_tc<<<g2, 128, SMEM_A>>>(slopes);

    dim3 g3(8, 32);                  // O projection
    gemm_tc<<<g3, 128, SMEM_G>>>(out, 1);
}

// round 15
// speedup vs baseline: 6.0755x; 1.7090x over previous
#include <cuda_runtime.h>
#include <cuda_fp16.h>
#include <math.h>
#include <stdint.h>

#define Bb 2
#define Ss 2048
#define Dd 1024
#define Hh 16
#define DHh 64
#define MM (Bb*Ss)
#define LOG2E 1.4426950408889634f

// Scratch (device globals). half2 payloads stored as uint32.
__device__ uint32_t g_x2[MM*Dd/2];        // X   [m][k/2] natural half2
__device__ uint32_t g_w2[4][Dd/2*Dd];     // W   [k/2][n] k-pair-interleaved half2
__device__ uint32_t g_q2[MM*Dd/2];        // Q   [m][d/2] natural, scale 0.125*log2e folded
__device__ uint32_t g_k2[MM*Dd/2];        // K   [m][d/2] natural
__device__ uint32_t g_v2[MM/2*Dd];        // V   [m/2][d] key-pair-interleaved half2
__device__ uint32_t g_att2[MM*Dd/2];      // att [m][d/2] natural

__device__ const float* g_bias_ptrs[4];
__global__ void set_bias_ptrs(const float* bq, const float* bk,
                              const float* bv, const float* bo) {
    g_bias_ptrs[0] = bq; g_bias_ptrs[1] = bk;
    g_bias_ptrs[2] = bv; g_bias_ptrs[3] = bo;
}

__device__ __forceinline__ uint32_t h2u(float lo, float hi) {
    __half2 h = __floats2half2_rn(lo, hi);
    return *reinterpret_cast<uint32_t*>(&h);
}
__device__ __forceinline__ float ex2(float x) {
    float r;
    asm("ex2.approx.f32 %0, %1;" : "=f"(r) : "f"(x));
    return r;
}

__device__ __forceinline__ void mma_f16(float* c, const uint32_t* a,
                                        uint32_t b0, uint32_t b1) {
    asm volatile("mma.sync.aligned.m16n8k16.row.col.f32.f16.f16.f32 "
        "{%0,%1,%2,%3}, {%4,%5,%6,%7}, {%8,%9}, {%0,%1,%2,%3};"
        : "+f"(c[0]), "+f"(c[1]), "+f"(c[2]), "+f"(c[3])
        : "r"(a[0]), "r"(a[1]), "r"(a[2]), "r"(a[3]), "r"(b0), "r"(b1));
}

__device__ __forceinline__ void cpa16(uint32_t dst, const void* src) {
    asm volatile("cp.async.cg.shared.global [%0], [%1], 16;\n" :: "r"(dst), "l"(src));
}
__device__ __forceinline__ void cp_commit() {
    asm volatile("cp.async.commit_group;\n" ::);
}
template<int N> __device__ __forceinline__ void cp_wait() {
    asm volatile("cp.async.wait_group %0;\n" :: "n"(N));
}

// ---------------------------------------------------------------------------
// Pre-convert: X fp32 -> natural half2
// ---------------------------------------------------------------------------
__global__ __launch_bounds__(256) void cvt_x(const float4* __restrict__ src, int n4)
{
    const int i = blockIdx.x * blockDim.x + threadIdx.x;
    if (i >= n4) return;
    float4 v = src[i];
    ((uint2*)g_x2)[i] = make_uint2(h2u(v.x, v.y), h2u(v.z, v.w));
}

// ---------------------------------------------------------------------------
// Pre-convert: W fp32 [k][n] -> k-pair-interleaved half2 [k/2][n]
// ---------------------------------------------------------------------------
__global__ __launch_bounds__(256) void cvt_w(const float* __restrict__ src, int which)
{
    const int i = blockIdx.x * blockDim.x + threadIdx.x;   // over 512*256
    const int kk = i >> 8;
    const int n  = (i & 255) * 4;
    float4 r0 = *(const float4*)&src[(size_t)(2*kk)   * Dd + n];
    float4 r1 = *(const float4*)&src[(size_t)(2*kk+1) * Dd + n];
    *(uint4*)&g_w2[which][(size_t)kk * Dd + n] =
        make_uint4(h2u(r0.x, r1.x), h2u(r0.y, r1.y),
                   h2u(r0.z, r1.z), h2u(r0.w, r1.w));
}

// ---------------------------------------------------------------------------
// fp16 GEMM, 3-stage cp.async pipeline. Block 128x128, BK=32, 4 warps.
// mode 0: grid(24,32) fused QKV -> g_q2/g_k2/g_v2 (half2; V interleaved)
// mode 1: grid(8,32)  g_att2 x Wo -> fp32 OUTP + bias
// Dyn smem: 3*(128*20 + 16*136)*4 = 56832 B.
// ---------------------------------------------------------------------------
__global__ __launch_bounds__(128, 2) void gemm_f16(float* __restrict__ OUTP, int mode)
{
    extern __shared__ uint32_t smem[];
    const uint32_t smaddr = (uint32_t)__cvta_generic_to_shared(smem);

    const uint32_t* A;
    const uint32_t* W;
    int sel, n0;
    if (mode == 0) {
        sel = blockIdx.x >> 3;
        A = g_x2;
        W = g_w2[sel];
        n0 = (blockIdx.x & 7) * 128;
    } else {
        sel = 3;
        A = g_att2;
        W = g_w2[3];
        n0 = blockIdx.x * 128;
    }
    const int m0 = blockIdx.y * 128;
    const int tid  = threadIdx.x;
    const int lane = tid & 31;
    const int warp = tid >> 5;
    const int wm = warp & 1;
    const int wn = warp >> 1;
    const int lr = lane >> 2;
    const int lc = lane & 3;

    float c[4][8][4];
    #pragma unroll
    for (int mi = 0; mi < 4; mi++)
        #pragma unroll
        for (int ni = 0; ni < 8; ni++)
            #pragma unroll
            for (int q = 0; q < 4; q++) c[mi][ni][q] = 0.f;

    const int ar  = tid >> 2;   // A rows ar + 32u   (half2 cols)
    const int ac4 = tid & 3;    // 16B chunk (4 half2) within 16-half2 k-tile
    const int bkr = tid >> 5;   // B kk-rows bkr + 4u
    const int bn4 = tid & 31;   // 16B chunk within 128-n row

    // stage layout: As[st] at st*2560 words, Bs[st] at 7680 + st*2176 words
    #define LOAD_STAGE(st, kk0) do {                                            \
        const uint32_t ab = smaddr + (uint32_t)(st)*2560*4;                     \
        const uint32_t bb = smaddr + (7680u + (uint32_t)(st)*2176u)*4;          \
        _Pragma("unroll")                                                       \
        for (int u = 0; u < 4; u++) {                                           \
            cpa16(ab + (uint32_t)((ar + 32*u)*20 + 4*ac4)*4,                    \
                  &A[(size_t)(m0 + ar + 32*u) * (Dd/2) + (kk0) + 4*ac4]);       \
            cpa16(bb + (uint32_t)((bkr + 4*u)*136 + 4*bn4)*4,                   \
                  &W[(size_t)((kk0) + bkr + 4*u) * Dd + n0 + 4*bn4]);           \
        }                                                                       \
    } while (0)

    LOAD_STAGE(0, 0);  cp_commit();
    LOAD_STAGE(1, 16); cp_commit();

    for (int kt = 0; kt < 32; kt++) {
        if (kt < 31) cp_wait<1>(); else cp_wait<0>();
        __syncthreads();
        if (kt < 30) {
            const int st = (kt + 2) % 3;
            LOAD_STAGE(st, (kt + 2) * 16);
            cp_commit();
        }
        const int buf = kt % 3;
        const uint32_t* as = smem + buf * 2560;
        const uint32_t* bs = smem + 7680 + buf * 2176;
        #pragma unroll
        for (int kc = 0; kc < 2; kc++) {
            uint32_t af[4][4], bf[8][2];
            #pragma unroll
            for (int mi = 0; mi < 4; mi++) {
                const int m = wm*64 + mi*16 + lr;
                af[mi][0] = as[m*20 + kc*8 + lc];
                af[mi][1] = as[(m + 8)*20 + kc*8 + lc];
                af[mi][2] = as[m*20 + kc*8 + lc + 4];
                af[mi][3] = as[(m + 8)*20 + kc*8 + lc + 4];
            }
            #pragma unroll
            for (int ni = 0; ni < 8; ni++) {
                const int n = wn*64 + ni*8 + lr;
                bf[ni][0] = bs[(kc*8 + lc)*136 + n];
                bf[ni][1] = bs[(kc*8 + lc + 4)*136 + n];
            }
            #pragma unroll
            for (int mi = 0; mi < 4; mi++)
                #pragma unroll
                for (int ni = 0; ni < 8; ni++)
                    mma_f16(c[mi][ni], af[mi], bf[ni][0], bf[ni][1]);
        }
    }
    #undef LOAD_STAGE

    const float* bias = g_bias_ptrs[sel];
    if (mode == 1) {
        #pragma unroll
        for (int mi = 0; mi < 4; mi++) {
            const int row = m0 + wm*64 + mi*16 + lr;
            #pragma unroll
            for (int ni = 0; ni < 8; ni++) {
                const int col = n0 + wn*64 + ni*8 + 2*lc;
                const float bx = bias[col], by = bias[col + 1];
                *(float2*)&OUTP[(size_t)row * Dd + col] =
                    make_float2(c[mi][ni][0] + bx, c[mi][ni][1] + by);
                *(float2*)&OUTP[(size_t)(row + 8) * Dd + col] =
                    make_float2(c[mi][ni][2] + bx, c[mi][ni][3] + by);
            }
        }
        return;
    }

    if (sel == 2) {
        // V: key-pair interleave. Exchange with row-partner (lr^1) via shfl,
        // even-lr threads store both (lr,lr+1) and (lr+8,lr+9) pairs.
        const unsigned FULL = 0xffffffffu;
        #pragma unroll
        for (int mi = 0; mi < 4; mi++) {
            const int row = m0 + wm*64 + mi*16 + lr;      // even rows for even lr
            #pragma unroll
            for (int ni = 0; ni < 8; ni++) {
                const int col = n0 + wn*64 + ni*8 + 2*lc;
                const float bx = bias[col], by = bias[col + 1];
                float v0 = c[mi][ni][0] + bx, v1 = c[mi][ni][1] + by;
                float v2 = c[mi][ni][2] + bx, v3 = c[mi][ni][3] + by;
                const float p0 = __shfl_xor_sync(FULL, v0, 4);
                const float p1 = __shfl_xor_sync(FULL, v1, 4);
                const float p2 = __shfl_xor_sync(FULL, v2, 4);
                const float p3 = __shfl_xor_sync(FULL, v3, 4);
                if (!(lr & 1)) {
                    const size_t kk0 = (size_t)(row >> 1) * Dd + col;
                    const size_t kk1 = (size_t)((row + 8) >> 1) * Dd + col;
                    *(uint2*)&g_v2[kk0] = make_uint2(h2u(v0, p0), h2u(v1, p1));
                    *(uint2*)&g_v2[kk1] = make_uint2(h2u(v2, p2), h2u(v3, p3));
                }
            }
        }
    } else {
        uint32_t* OUTU = (sel == 0) ? g_q2 : g_k2;
        const float qs = (sel == 0) ? (0.125f * LOG2E) : 1.0f;
        #pragma unroll
        for (int mi = 0; mi < 4; mi++) {
            const int row = m0 + wm*64 + mi*16 + lr;
            #pragma unroll
            for (int ni = 0; ni < 8; ni++) {
                const int col = n0 + wn*64 + ni*8 + 2*lc;
                const float bx = bias[col], by = bias[col + 1];
                const int ch = col >> 1;
                OUTU[(size_t)row * (Dd/2) + ch] =
                    h2u((c[mi][ni][0] + bx) * qs, (c[mi][ni][1] + by) * qs);
                OUTU[(size_t)(row + 8) * (Dd/2) + ch] =
                    h2u((c[mi][ni][2] + bx) * qs, (c[mi][ni][3] + by) * qs);
            }
        }
    }
}

// ---------------------------------------------------------------------------
// Flash attention fp16: 64-q blocks, 128 threads (2 q-groups x 2 key-halves),
// per-half log2-domain online softmax, end merge. 2-stage cp.async K/V.
// S C-frag == PV A-frag layout (fp16 m16n8k16): zero-shuffle P transform.
// Smem words/stage: K 64*36=2304, V 32*72=2304 -> 2*(2304+2304)*4 = 36864 B.
// ---------------------------------------------------------------------------
__global__ __launch_bounds__(128, 2) void attn_f16(const float* __restrict__ slopes)
{
    extern __shared__ uint32_t smem[];
    const uint32_t smaddr = (uint32_t)__cvta_generic_to_shared(smem);
    // Ks[st] at st*2304 words ; Vs[st] at 4608 + st*2304 words

    const int tid  = threadIdx.x;
    const int lane = tid & 31;
    const int warp = tid >> 5;
    const int qw = warp >> 1;
    const int kh = warp & 1;
    const int lr = lane >> 2;
    const int lc = lane & 3;
    const int b  = blockIdx.y >> 4;
    const int h  = blockIdx.y & (Hh - 1);
    const int q0 = blockIdx.x * 64;

    const float sp2 = log1pf(expf(slopes[h])) * LOG2E;   // softplus * log2e
    const unsigned FULL = 0xffffffffu;

    // Persistent Q A-frags (half2, 0.125*log2e folded at producer)
    uint32_t qf[2][4][4];
    {
        const size_t rq = (size_t)(b*Ss + q0 + qw*32 + lr) * (Dd/2) + h*32;
        #pragma unroll
        for (int mi = 0; mi < 2; mi++) {
            const size_t r0 = rq + (size_t)(mi*16) * (Dd/2);
            const size_t r1 = r0 + (size_t)8 * (Dd/2);
            #pragma unroll
            for (int kc = 0; kc < 4; kc++) {
                qf[mi][kc][0] = g_q2[r0 + kc*8 + lc];
                qf[mi][kc][1] = g_q2[r1 + kc*8 + lc];
                qf[mi][kc][2] = g_q2[r0 + kc*8 + lc + 4];
                qf[mi][kc][3] = g_q2[r1 + kc*8 + lc + 4];
            }
        }
    }

    float o[2][8][4];
    #pragma unroll
    for (int mi = 0; mi < 2; mi++)
        #pragma unroll
        for (int nd = 0; nd < 8; nd++)
            #pragma unroll
            for (int q = 0; q < 4; q++) o[mi][nd][q] = 0.f;

    float m_r[2][2], l_r[2][2];
    #pragma unroll
    for (int mi = 0; mi < 2; mi++)
        #pragma unroll
        for (int rh = 0; rh < 2; rh++) { m_r[mi][rh] = -1e30f; l_r[mi][rh] = 0.f; }

    const float qr_base = (float)(q0 + qw*32 + lr);

    // K tile: 64 rows x 32 half2 (stride 36). V tile: 32 kk-rows x 64 half2 (stride 72).
    #define LOAD_KV(st, k0v) do {                                               \
        const uint32_t kb_ = smaddr + (uint32_t)(st)*2304u*4;                   \
        const uint32_t vb_ = smaddr + (4608u + (uint32_t)(st)*2304u)*4;         \
        _Pragma("unroll")                                                       \
        for (int i_ = 0; i_ < 4; i_++) {                                        \
            const int ck = tid + i_*128;          /* 0..511 */                  \
            const int key = ck >> 3;                                            \
            const int kc4 = (ck & 7) * 4;                                       \
            cpa16(kb_ + (uint32_t)(key*36 + kc4)*4,                             \
                  &g_k2[(size_t)(b*Ss + (k0v) + key)*(Dd/2) + h*32 + kc4]);     \
            const int vr = ck >> 4;               /* 0..31 */                   \
            const int vc4 = (ck & 15) * 4;                                      \
            cpa16(vb_ + (uint32_t)(vr*72 + vc4)*4,                              \
                  &g_v2[(size_t)(((b*Ss + (k0v)) >> 1) + vr)*Dd + h*64 + vc4]); \
        }                                                                       \
    } while (0)

    LOAD_KV(0, 0); cp_commit();

    for (int t = 0; t < Ss/64; t++) {
        const int k0 = t * 64;
        __syncthreads();
        if (t + 1 < Ss/64) {
            LOAD_KV((t + 1) & 1, k0 + 64);
            cp_commit();
            cp_wait<1>();
        } else {
            cp_wait<0>();
        }
        __syncthreads();

        const uint32_t* ks = smem + (t & 1) * 2304;
        const uint32_t* vs = smem + 4608 + (t & 1) * 2304;

        // S = Q K^T (warp: 32q x 32key of its half), k=64 in 4 chunks of 16
        float sc[2][4][4];
        #pragma unroll
        for (int mi = 0; mi < 2; mi++)
            #pragma unroll
            for (int ni = 0; ni < 4; ni++)
                #pragma unroll
                for (int q = 0; q < 4; q++) sc[mi][ni][q] = 0.f;
        #pragma unroll
        for (int kc = 0; kc < 4; kc++) {
            uint32_t kb0[4], kb1[4];
            #pragma unroll
            for (int ni = 0; ni < 4; ni++) {
                const uint32_t* kr = ks + (kh*32 + ni*8 + lr)*36 + kc*8 + lc;
                kb0[ni] = kr[0];
                kb1[ni] = kr[4];
            }
            #pragma unroll
            for (int mi = 0; mi < 2; mi++)
                #pragma unroll
                for (int ni = 0; ni < 4; ni++)
                    mma_f16(sc[mi][ni], qf[mi][kc], kb0[ni], kb1[ni]);
        }

        // ALiBi bias (log2 domain) + per-half online softmax (ex2)
        float scl[2][2];
        #pragma unroll
        for (int mi = 0; mi < 2; mi++) {
            const float qr0 = qr_base + (float)(mi*16);
            const float qr1 = qr0 + 8.f;
            float p0 = -1e30f, p1 = -1e30f;
            #pragma unroll
            for (int ni = 0; ni < 4; ni++) {
                const float kp = (float)(k0 + kh*32 + ni*8 + 2*lc);
                sc[mi][ni][0] = fmaf(-sp2, fabsf(qr0 - kp),       sc[mi][ni][0]);
                sc[mi][ni][1] = fmaf(-sp2, fabsf(qr0 - (kp+1.f)), sc[mi][ni][1]);
                sc[mi][ni][2] = fmaf(-sp2, fabsf(qr1 - kp),       sc[mi][ni][2]);
                sc[mi][ni][3] = fmaf(-sp2, fabsf(qr1 - (kp+1.f)), sc[mi][ni][3]);
                p0 = fmaxf(p0, fmaxf(sc[mi][ni][0], sc[mi][ni][1]));
                p1 = fmaxf(p1, fmaxf(sc[mi][ni][2], sc[mi][ni][3]));
            }
            p0 = fmaxf(p0, __shfl_xor_sync(FULL, p0, 1));
            p0 = fmaxf(p0, __shfl_xor_sync(FULL, p0, 2));
            p1 = fmaxf(p1, __shfl_xor_sync(FULL, p1, 1));
            p1 = fmaxf(p1, __shfl_xor_sync(FULL, p1, 2));
            const float mn0 = fmaxf(m_r[mi][0], p0);
            const float mn1 = fmaxf(m_r[mi][1], p1);
            scl[mi][0] = ex2(m_r[mi][0] - mn0);
            scl[mi][1] = ex2(m_r[mi][1] - mn1);
            m_r[mi][0] = mn0; m_r[mi][1] = mn1;
            float s0 = 0.f, s1 = 0.f;
            #pragma unroll
            for (int ni = 0; ni < 4; ni++) {
                sc[mi][ni][0] = ex2(sc[mi][ni][0] - mn0);
                sc[mi][ni][1] = ex2(sc[mi][ni][1] - mn0);
                sc[mi][ni][2] = ex2(sc[mi][ni][2] - mn1);
                sc[mi][ni][3] = ex2(sc[mi][ni][3] - mn1);
                s0 += sc[mi][ni][0] + sc[mi][ni][1];
                s1 += sc[mi][ni][2] + sc[mi][ni][3];
            }
            s0 += __shfl_xor_sync(FULL, s0, 1);
            s0 += __shfl_xor_sync(FULL, s0, 2);
            s1 += __shfl_xor_sync(FULL, s1, 1);
            s1 += __shfl_xor_sync(FULL, s1, 2);
            l_r[mi][0] = l_r[mi][0] * scl[mi][0] + s0;
            l_r[mi][1] = l_r[mi][1] * scl[mi][1] + s1;
        }

        // Rescale O; P C-frag -> A-frag by local half2 packing (no shuffles); PV
        #pragma unroll
        for (int mi = 0; mi < 2; mi++)
            #pragma unroll
            for (int nd = 0; nd < 8; nd++) {
                o[mi][nd][0] *= scl[mi][0]; o[mi][nd][1] *= scl[mi][0];
                o[mi][nd][2] *= scl[mi][1]; o[mi][nd][3] *= scl[mi][1];
            }
        #pragma unroll
        for (int kc = 0; kc < 2; kc++) {       // key chunks of 16
            uint32_t pa[2][4];
            #pragma unroll
            for (int mi = 0; mi < 2; mi++) {
                pa[mi][0] = h2u(sc[mi][2*kc][0],   sc[mi][2*kc][1]);
                pa[mi][1] = h2u(sc[mi][2*kc][2],   sc[mi][2*kc][3]);
                pa[mi][2] = h2u(sc[mi][2*kc+1][0], sc[mi][2*kc+1][1]);
                pa[mi][3] = h2u(sc[mi][2*kc+1][2], sc[mi][2*kc+1][3]);
            }
            const uint32_t* vr0 = vs + (kh*16 + kc*8 + lc)*72;
            const uint32_t* vr1 = vr0 + 4*72;
            #pragma unroll
            for (int nd = 0; nd < 8; nd++) {
                const uint32_t b0 = vr0[nd*8 + lr];
                const uint32_t b1 = vr1[nd*8 + lr];
                mma_f16(o[0][nd], pa[0], b0, b1);
                mma_f16(o[1][nd], pa[1], b0, b1);
            }
        }
    }
    #undef LOAD_KV

    // Merge the two key-half partials (log2-domain m) through reused smem.
    __syncthreads();
    float* Ob = (float*)smem;   // [64] rows x 68 floats: 64 O cols, m@64, l@65
    if (kh == 0) {
        #pragma unroll
        for (int mi = 0; mi < 2; mi++) {
            const int r0 = qw*32 + mi*16 + lr;
            #pragma unroll
            for (int nd = 0; nd < 8; nd++) {
                const int cc = nd*8 + 2*lc;
                *(float2*)&Ob[r0*68 + cc]     = make_float2(o[mi][nd][0], o[mi][nd][1]);
                *(float2*)&Ob[(r0+8)*68 + cc] = make_float2(o[mi][nd][2], o[mi][nd][3]);
            }
            if (lc == 0) {
                Ob[r0*68 + 64]     = m_r[mi][0];
                Ob[r0*68 + 65]     = l_r[mi][0];
                Ob[(r0+8)*68 + 64] = m_r[mi][1];
                Ob[(r0+8)*68 + 65] = l_r[mi][1];
            }
        }
    }
    __syncthreads();
    if (kh == 1) {
        #pragma unroll
        for (int mi = 0; mi < 2; mi++) {
            float A0[2], A1[2];
            #pragma unroll
            for (int rh = 0; rh < 2; rh++) {
                const int row = qw*32 + mi*16 + rh*8 + lr;
                const float m0 = Ob[row*68 + 64];
                const float l0 = Ob[row*68 + 65];
                const float m1 = m_r[mi][rh];
                const float mm = fmaxf(m0, m1);
                const float e0 = ex2(m0 - mm);
                const float e1 = ex2(m1 - mm);
                const float inv = 1.f / (l0*e0 + l_r[mi][rh]*e1);
                A0[rh] = e0 * inv;
                A1[rh] = e1 * inv;
            }
            const int r0 = qw*32 + mi*16 + lr;
            const size_t g0 = (size_t)(b*Ss + q0 + r0) * (Dd/2) + h*32;
            const size_t g1 = g0 + (size_t)8 * (Dd/2);
            #pragma unroll
            for (int nd = 0; nd < 8; nd++) {
                const int cc = nd*8 + 2*lc;
                float2 p0 = *(float2*)&Ob[r0*68 + cc];
                float2 p1 = *(float2*)&Ob[(r0+8)*68 + cc];
                g_att2[g0 + (cc >> 1)] = h2u(p0.x*A0[0] + o[mi][nd][0]*A1[0],
                                             p0.y*A0[0] + o[mi][nd][1]*A1[0]);
                g_att2[g1 + (cc >> 1)] = h2u(p1.x*A0[1] + o[mi][nd][2]*A1[1],
                                             p1.y*A0[1] + o[mi][nd][3]*A1[1]);
            }
        }
    }
}

extern "C" void kernel_launch(void* const* d_in, const int* in_sizes, int n_in,
                              void* d_out, int out_size)
{
    const float* x      = (const float*)d_in[0];
    const float* Wq     = (const float*)d_in[1];
    const float* bq     = (const float*)d_in[2];
    const float* Wk     = (const float*)d_in[3];
    const float* bk     = (const float*)d_in[4];
    const float* Wv     = (const float*)d_in[5];
    const float* bv     = (const float*)d_in[6];
    const float* Wo     = (const float*)d_in[7];
    const float* bo     = (const float*)d_in[8];
    const float* slopes = (const float*)d_in[9];
    float* out = (float*)d_out;

    static const int SMEM_G = 3 * (128*20 + 16*136) * 4;   // 56832
    static const int SMEM_A = 2 * (64*36 + 32*72) * 4;     // 36864
    cudaFuncSetAttribute(gemm_f16, cudaFuncAttributeMaxDynamicSharedMemorySize, SMEM_G);
    cudaFuncSetAttribute(attn_f16, cudaFuncAttributeMaxDynamicSharedMemorySize, SMEM_A);

    set_bias_ptrs<<<1, 1>>>(bq, bk, bv, bo);

    cvt_x<<<MM*Dd/4/256, 256>>>((const float4*)x, MM*Dd/4);
    cvt_w<<<Dd/2*Dd/4/256, 256>>>(Wq, 0);
    cvt_w<<<Dd/2*Dd/4/256, 256>>>(Wk, 1);
    cvt_w<<<Dd/2*Dd/4/256, 256>>>(Wv, 2);
    cvt_w<<<Dd/2*Dd/4/256, 256>>>(Wo, 3);

    dim3 g1(24, 32);                 // fused QKV
    gemm_f16<<<g1, 128, SMEM_G>>>(nullptr, 0);

    dim3 g2(Ss / 64, Bb * Hh);       // attention
    attn_f16<<<g2, 128, SMEM_A>>>(slopes);

    dim3 g3(8, 32);                  // O projection
    gemm_f16<<<g3, 128, SMEM_G>>>(out, 1);
}